// round 3
// baseline (speedup 1.0000x reference)
#include <cuda_runtime.h>
#include <cstdint>
#include <cstddef>

#define NB   32
#define NS   512
#define ND   512
#define NH2  256
#define NG3  768
#define NDK  64

// ------------------------- scratch (device globals) -------------------------
__device__ float g_xg[(size_t)2 * NB * NS * NG3];   // gate preactivations, per dir
__device__ float g_gru[(size_t)NB * NS * ND];       // concat GRU outputs
__device__ float g_ln1[(size_t)NB * NS * ND];       // ln1("outputs")
__device__ float g_q [(size_t)NB * 8 * NS * NDK];   // (b,h,s,d)
__device__ float g_k [(size_t)NB * 8 * NS * NDK];   // (b,h,s,d)
__device__ float g_vt[(size_t)NB * 8 * NDK * NS];   // (b,h,d,s)
__device__ float g_sc[(size_t)NB * 8 * NS * NS];    // scores -> p
__device__ float g_cc[(size_t)NB * NS * ND];        // attn concat
__device__ float g_o [(size_t)NB * NS * ND];        // out projection

// ------------------------- f32x2 helpers -------------------------
__device__ __forceinline__ unsigned long long fma2(unsigned long long a,
                                                   unsigned long long b,
                                                   unsigned long long c) {
    unsigned long long d;
    asm("fma.rn.f32x2 %0, %1, %2, %3;" : "=l"(d) : "l"(a), "l"(b), "l"(c));
    return d;
}
__device__ __forceinline__ unsigned long long pack2(float x, float y) {
    unsigned long long d;
    asm("mov.b64 %0, {%1, %2};" : "=l"(d) : "f"(x), "f"(y));
    return d;
}
__device__ __forceinline__ void unpack2(unsigned long long v, float& x, float& y) {
    asm("mov.b64 {%0, %1}, %2;" : "=f"(x), "=f"(y) : "l"(v));
}

// ------------------------- generic TN GEMM -------------------------
// C = epi(A[M,K] @ W[N,K]^T). modes:
// 0: +bias              1: +bias, scatter (b,h,s,d)   2: +bias, scatter (b,h,d,s)
// 3: *scale             4: scatter concat (b,s,h*64+d) 5: +bias, *rowmask(masks)
__device__ __forceinline__ void store_elem(float* C, const float* bias,
                                           const int* masks, int mode, float scale,
                                           int z, int N, int mrow, int nc, float v) {
    if (nc >= N) return;
    if (mode == 0) {
        C[(long)mrow * N + nc] = v + bias[nc];
    } else if (mode == 1) {
        int b = mrow >> 9, s = mrow & 511, h = nc >> 6, d = nc & 63;
        C[(((long)(b * 8 + h) * NS + s)) * NDK + d] = v + bias[nc];
    } else if (mode == 2) {
        int b = mrow >> 9, s = mrow & 511, h = nc >> 6, d = nc & 63;
        C[((long)(b * 8 + h) * NDK + d) * NS + s] = v + bias[nc];
    } else if (mode == 3) {
        C[(long)mrow * N + nc] = v * scale;
    } else if (mode == 4) {
        int b = z >> 3, h = z & 7;
        C[((long)(b * NS + mrow)) * ND + h * NDK + nc] = v;
    } else {
        C[(long)mrow * N + nc] = masks[mrow] ? (v + bias[nc]) : 0.f;
    }
}

__global__ void __launch_bounds__(256) gemm_tn(
    const float* __restrict__ A, const float* __restrict__ W,
    const float* __restrict__ bias, float* __restrict__ C,
    int M, int N, int K, long sA, long sW, long sC,
    int mode, float scale, const int* __restrict__ masks)
{
    __shared__ float As[8][128];
    __shared__ float Ws[8][128];

    const int z = blockIdx.z;
    A += (long)z * sA;
    W += (long)z * sW;
    if (mode == 0 || mode == 3) C += (long)z * sC;

    const int m0 = blockIdx.y * 128, n0 = blockIdx.x * 128;
    const int tid = threadIdx.x;
    const int lrow = tid >> 1, lkq = tid & 1;
    const int tx = tid & 15, ty = tid >> 4;
    const bool wok = (n0 + lrow) < N;
    const float* Ap = A + (long)(m0 + lrow) * K + lkq * 4;
    const float* Wp = W + (long)(n0 + lrow) * K + lkq * 4;

    unsigned long long acc[8][4];
#pragma unroll
    for (int i = 0; i < 8; i++) {
        acc[i][0] = 0ull; acc[i][1] = 0ull; acc[i][2] = 0ull; acc[i][3] = 0ull;
    }

    float4 av = *(const float4*)Ap;
    float4 wv = wok ? *(const float4*)Wp : make_float4(0.f, 0.f, 0.f, 0.f);

    for (int k0 = 0; k0 < K; k0 += 8) {
        __syncthreads();
        As[lkq * 4 + 0][lrow] = av.x; As[lkq * 4 + 1][lrow] = av.y;
        As[lkq * 4 + 2][lrow] = av.z; As[lkq * 4 + 3][lrow] = av.w;
        Ws[lkq * 4 + 0][lrow] = wv.x; Ws[lkq * 4 + 1][lrow] = wv.y;
        Ws[lkq * 4 + 2][lrow] = wv.z; Ws[lkq * 4 + 3][lrow] = wv.w;
        __syncthreads();
        if (k0 + 8 < K) {
            av = *(const float4*)(Ap + k0 + 8);
            wv = wok ? *(const float4*)(Wp + k0 + 8) : make_float4(0.f, 0.f, 0.f, 0.f);
        }
#pragma unroll
        for (int kk = 0; kk < 8; kk++) {
            float4 a0 = *(const float4*)&As[kk][ty * 4];
            float4 a1 = *(const float4*)&As[kk][ty * 4 + 64];
            ulonglong2 w0 = *(const ulonglong2*)&Ws[kk][tx * 4];
            ulonglong2 w1 = *(const ulonglong2*)&Ws[kk][tx * 4 + 64];
            unsigned long long ap[8];
            ap[0] = pack2(a0.x, a0.x); ap[1] = pack2(a0.y, a0.y);
            ap[2] = pack2(a0.z, a0.z); ap[3] = pack2(a0.w, a0.w);
            ap[4] = pack2(a1.x, a1.x); ap[5] = pack2(a1.y, a1.y);
            ap[6] = pack2(a1.z, a1.z); ap[7] = pack2(a1.w, a1.w);
#pragma unroll
            for (int i = 0; i < 8; i++) {
                acc[i][0] = fma2(ap[i], w0.x, acc[i][0]);
                acc[i][1] = fma2(ap[i], w0.y, acc[i][1]);
                acc[i][2] = fma2(ap[i], w1.x, acc[i][2]);
                acc[i][3] = fma2(ap[i], w1.y, acc[i][3]);
            }
        }
    }

#pragma unroll
    for (int i = 0; i < 8; i++) {
        int mrow = m0 + ty * 4 + (i & 3) + (i >> 2) * 64;
#pragma unroll
        for (int jp = 0; jp < 4; jp++) {
            float lo, hi;
            unpack2(acc[i][jp], lo, hi);
            int nc = n0 + tx * 4 + (jp & 1) * 2 + (jp >> 1) * 64;
            store_elem(C, bias, masks, mode, scale, z, N, mrow, nc, lo);
            store_elem(C, bias, masks, mode, scale, z, N, mrow, nc + 1, hi);
        }
    }
}

// ------------------------- persistent GRU (clusters + DSMEM) -------------------------
// 128 blocks = 16 clusters of 8. cluster = (dir, batchgroup of 4 batches),
// rank jc in [0,8) owns j-chunk of 32 hidden units. 384 threads:
// (r in [0,96)) x (kq in [0,4)); recurrent weights register-resident.
// h broadcast each step via st.shared::cluster into all 8 ranks' smem
// (double-buffered), one barrier.cluster per step.
__global__ void __launch_bounds__(384, 1) __cluster_dims__(8, 1, 1)
gru_kernel(
    const float* __restrict__ whf, const float* __restrict__ whb,
    const float* __restrict__ bhf, const float* __restrict__ bhb,
    const int* __restrict__ masks, float* __restrict__ hid_out)
{
    __shared__ float sh_h[2][1024];  // [buf][b][k] full h for 4 batches
    __shared__ float sh_part[1536];  // [r][b][kq]
    __shared__ float sh_gate[384];   // [r][b]

    const int bid = blockIdx.x;
    const int jc  = bid & 7;         // cluster rank
    const int cl  = bid >> 3;
    const int dir = cl >> 3;
    const int bg  = cl & 7;
    const int tid = threadIdx.x;
    const int r   = tid >> 2;        // 0..95 (gate-row in block)
    const int kq  = tid & 3;         // k quarter
    const int G   = (r >> 5) * 256 + jc * 32 + (r & 31);

    const float* wh = dir ? whb : whf;
    const float* bh = dir ? bhb : bhf;
    const float bhh = bh[G];

    unsigned long long wp[32];
    {
        const float* ws = wh + (long)G * NH2 + kq * 64;
#pragma unroll
        for (int i = 0; i < 32; i++) wp[i] = pack2(ws[2 * i], ws[2 * i + 1]);
    }

    const int ju = tid & 31, bu = tid >> 5;   // updater role (tid < 128)
    const int jglob = jc * 32 + ju;
    const int bglob = bg * 4 + bu;
    const float* xgp = g_xg + ((size_t)dir * NB + bglob) * NS * NG3;

    const uint32_t sh_base =
        (uint32_t)__cvta_generic_to_shared(&sh_h[0][0]);

    for (int i = tid; i < 1024; i += 384) sh_h[0][i] = 0.f;
    float hreg = 0.f;
    // cluster-wide: everyone's smem initialized before any remote store lands
    asm volatile("barrier.cluster.arrive.aligned;" ::: "memory");
    asm volatile("barrier.cluster.wait.aligned;"   ::: "memory");

    for (int t = 0; t < NS; t++) {
        const int s = dir ? (NS - 1 - t) : t;
        float xr = 0.f, xz = 0.f, xn = 0.f;
        int mk = 0;
        if (tid < 128) {  // prefetch x-gates + mask (independent of h)
            const float* xrow = xgp + (size_t)s * NG3;
            xr = __ldg(xrow + jglob);
            xz = __ldg(xrow + NH2 + jglob);
            xn = __ldg(xrow + 2 * NH2 + jglob);
            mk = __ldg(masks + bglob * NS + s);
        }
        // hg partial dot products (f32x2) from current buffer
        const float* hp = sh_h[t & 1];
        unsigned long long acc[4] = {0ull, 0ull, 0ull, 0ull};
#pragma unroll
        for (int i = 0; i < 16; i++) {
#pragma unroll
            for (int b = 0; b < 4; b++) {
                ulonglong2 hv = *(const ulonglong2*)(hp + b * 256 + kq * 64 + i * 4);
                acc[b] = fma2(wp[2 * i],     hv.x, acc[b]);
                acc[b] = fma2(wp[2 * i + 1], hv.y, acc[b]);
            }
        }
#pragma unroll
        for (int b = 0; b < 4; b++) {
            float lo, hi;
            unpack2(acc[b], lo, hi);
            sh_part[r * 16 + b * 4 + kq] = lo + hi;
        }
        __syncthreads();
        {   // k-quarter reduction: thread -> (r, b2=kq)
            const int base = r * 16 + kq * 4;
            sh_gate[r * 4 + kq] = sh_part[base] + sh_part[base + 1] +
                                  sh_part[base + 2] + sh_part[base + 3] + bhh;
        }
        __syncthreads();
        if (tid < 128) {
            const float hgr = sh_gate[ju * 4 + bu];
            const float hgz = sh_gate[(32 + ju) * 4 + bu];
            const float hgn = sh_gate[(64 + ju) * 4 + bu];
            const float rr = 1.f / (1.f + __expf(-(xr + hgr)));
            const float zz = 1.f / (1.f + __expf(-(xz + hgz)));
            const float na = xn + rr * hgn;
            const float nn = 2.f / (1.f + __expf(-2.f * na)) - 1.f;  // tanh
            const float hnew = (1.f - zz) * nn + zz * hreg;
            hreg = mk ? hnew : hreg;
            g_gru[((size_t)bglob * NS + s) * ND + dir * NH2 + jglob] = mk ? hreg : 0.f;
            if (t == NS - 1) {
                hid_out[bglob * ND + dir * NH2 + jglob] = hreg;
            } else {
                // broadcast h into next buffer of all 8 cluster ranks
                const uint32_t dst = sh_base +
                    (uint32_t)((((t + 1) & 1) * 1024 + bu * 256 + jglob) * 4);
#pragma unroll
                for (int rk = 0; rk < 8; rk++) {
                    uint32_t ra;
                    asm("mapa.shared::cluster.u32 %0, %1, %2;"
                        : "=r"(ra) : "r"(dst), "r"(rk));
                    asm volatile("st.shared::cluster.f32 [%0], %1;"
                                 :: "r"(ra), "f"(hreg) : "memory");
                }
            }
        }
        if (t < NS - 1) {
            asm volatile("barrier.cluster.arrive.aligned;" ::: "memory");
            asm volatile("barrier.cluster.wait.aligned;"   ::: "memory");
        }
    }
}

// ------------------------- layernorm (optionally fused residual) -------------------------
__global__ void __launch_bounds__(128) ln_kernel(
    const float* __restrict__ x, const float* __restrict__ y,
    const float* __restrict__ gam, const float* __restrict__ bet,
    float* __restrict__ out)
{
    __shared__ float red[8];
    const int row = blockIdx.x;
    const int tid = threadIdx.x;
    float4 v = *(const float4*)(x + (size_t)row * ND + tid * 4);
    if (y) {
        float4 w = *(const float4*)(y + (size_t)row * ND + tid * 4);
        v.x += w.x; v.y += w.y; v.z += w.z; v.w += w.w;
    }
    float s1 = v.x + v.y + v.z + v.w;
    float s2 = v.x * v.x + v.y * v.y + v.z * v.z + v.w * v.w;
#pragma unroll
    for (int o = 16; o; o >>= 1) {
        s1 += __shfl_xor_sync(~0u, s1, o);
        s2 += __shfl_xor_sync(~0u, s2, o);
    }
    const int wid = tid >> 5;
    if ((tid & 31) == 0) { red[wid] = s1; red[wid + 4] = s2; }
    __syncthreads();
    s1 = red[0] + red[1] + red[2] + red[3];
    s2 = red[4] + red[5] + red[6] + red[7];
    const float mu = s1 * (1.f / ND);
    const float var = s2 * (1.f / ND) - mu * mu;
    const float rs = rsqrtf(var + 1e-5f);
    const float4 gv = *(const float4*)(gam + tid * 4);
    const float4 bv = *(const float4*)(bet + tid * 4);
    float4 o4;
    o4.x = (v.x - mu) * rs * gv.x + bv.x;
    o4.y = (v.y - mu) * rs * gv.y + bv.y;
    o4.z = (v.z - mu) * rs * gv.z + bv.z;
    o4.w = (v.w - mu) * rs * gv.w + bv.w;
    *(float4*)(out + (size_t)row * ND + tid * 4) = o4;
}

// ------------------------- masked prefix softmax -------------------------
__global__ void __launch_bounds__(128) softmax_kernel(
    float* __restrict__ P, const int* __restrict__ lengths)
{
    __shared__ float red[4];
    const int q = blockIdx.x, z = blockIdx.y;
    const int len = __ldg(lengths + (z >> 3));
    float* row = P + ((size_t)z * NS + q) * NS;
    const int tid = threadIdx.x;
    const int c0 = tid * 4;
    if (q >= len) {
        *(float4*)(row + c0) = make_float4(0.f, 0.f, 0.f, 0.f);
        return;
    }
    float4 v = *(const float4*)(row + c0);
    const bool b0 = c0 < len, b1 = c0 + 1 < len, b2 = c0 + 2 < len, b3 = c0 + 3 < len;
    float m = -1e30f;
    if (b0) m = fmaxf(m, v.x);
    if (b1) m = fmaxf(m, v.y);
    if (b2) m = fmaxf(m, v.z);
    if (b3) m = fmaxf(m, v.w);
#pragma unroll
    for (int o = 16; o; o >>= 1) m = fmaxf(m, __shfl_xor_sync(~0u, m, o));
    const int wid = tid >> 5;
    if ((tid & 31) == 0) red[wid] = m;
    __syncthreads();
    m = fmaxf(fmaxf(red[0], red[1]), fmaxf(red[2], red[3]));
    __syncthreads();
    float4 e;
    e.x = b0 ? __expf(v.x - m) : 0.f;
    e.y = b1 ? __expf(v.y - m) : 0.f;
    e.z = b2 ? __expf(v.z - m) : 0.f;
    e.w = b3 ? __expf(v.w - m) : 0.f;
    float s = e.x + e.y + e.z + e.w;
#pragma unroll
    for (int o = 16; o; o >>= 1) s += __shfl_xor_sync(~0u, s, o);
    if ((tid & 31) == 0) red[wid] = s;
    __syncthreads();
    s = red[0] + red[1] + red[2] + red[3];
    const float inv = 1.f / s;
    e.x *= inv; e.y *= inv; e.z *= inv; e.w *= inv;
    *(float4*)(row + c0) = e;
}

// ------------------------- launch -------------------------
extern "C" void kernel_launch(void* const* d_in, const int* in_sizes, int n_in,
                              void* d_out, int out_size)
{
    const float* splits = (const float*)d_in[0];
    const float* w_ih_f = (const float*)d_in[1];
    const float* w_hh_f = (const float*)d_in[2];
    const float* b_ih_f = (const float*)d_in[3];
    const float* b_hh_f = (const float*)d_in[4];
    const float* w_ih_b = (const float*)d_in[5];
    const float* w_hh_b = (const float*)d_in[6];
    const float* b_ih_b = (const float*)d_in[7];
    const float* b_hh_b = (const float*)d_in[8];
    const float* ln1_g  = (const float*)d_in[9];
    const float* ln1_b  = (const float*)d_in[10];
    const float* wq = (const float*)d_in[11];
    const float* bq = (const float*)d_in[12];
    const float* wk = (const float*)d_in[13];
    const float* bk = (const float*)d_in[14];
    const float* wv = (const float*)d_in[15];
    const float* bv = (const float*)d_in[16];
    const float* wo = (const float*)d_in[17];
    const float* bo = (const float*)d_in[18];
    const float* ln2_g = (const float*)d_in[19];
    const float* ln2_b = (const float*)d_in[20];
    const int* lengths = (const int*)d_in[21];
    const int* masks   = (const int*)d_in[22];
    float* out = (float*)d_out;

    float *xg, *gru, *ln1, *q, *k, *vt, *sc, *cc, *oo;
    cudaGetSymbolAddress((void**)&xg,  g_xg);
    cudaGetSymbolAddress((void**)&gru, g_gru);
    cudaGetSymbolAddress((void**)&ln1, g_ln1);
    cudaGetSymbolAddress((void**)&q,   g_q);
    cudaGetSymbolAddress((void**)&k,   g_k);
    cudaGetSymbolAddress((void**)&vt,  g_vt);
    cudaGetSymbolAddress((void**)&sc,  g_sc);
    cudaGetSymbolAddress((void**)&cc,  g_cc);
    cudaGetSymbolAddress((void**)&oo,  g_o);

    const int M = NB * NS;  // 16384

    // GRU input projections (both dirs)
    gemm_tn<<<dim3(6, 128, 1), 256>>>(splits, w_ih_f, b_ih_f, xg,
                                      M, NG3, ND, 0, 0, 0, 0, 1.f, nullptr);
    gemm_tn<<<dim3(6, 128, 1), 256>>>(splits, w_ih_b, b_ih_b, xg + (size_t)M * NG3,
                                      M, NG3, ND, 0, 0, 0, 0, 1.f, nullptr);
    // GRU recurrence (16 clusters of 8, DSMEM h-broadcast)
    gru_kernel<<<128, 384>>>(w_hh_f, w_hh_b, b_hh_f, b_hh_b, masks,
                             out + (size_t)NB * NS * ND);
    // LN1
    ln_kernel<<<M, 128>>>(gru, nullptr, ln1_g, ln1_b, ln1);
    // Q/K/V projections with head scatter
    gemm_tn<<<dim3(4, 128, 1), 256>>>(ln1, wq, bq, q,  M, ND, ND, 0, 0, 0, 1, 1.f, nullptr);
    gemm_tn<<<dim3(4, 128, 1), 256>>>(ln1, wk, bk, k,  M, ND, ND, 0, 0, 0, 1, 1.f, nullptr);
    gemm_tn<<<dim3(4, 128, 1), 256>>>(ln1, wv, bv, vt, M, ND, ND, 0, 0, 0, 2, 1.f, nullptr);
    // scores = q @ k^T / 8   (z = b*8+h)
    gemm_tn<<<dim3(4, 4, 256), 256>>>(q, k, nullptr, sc, NS, NS, NDK,
                                      (long)NS * NDK, (long)NS * NDK, (long)NS * NS,
                                      3, 0.125f, nullptr);
    // masked prefix softmax (in place)
    softmax_kernel<<<dim3(NS, 256), 128>>>(sc, lengths);
    // attn = p @ v  -> concat layout
    gemm_tn<<<dim3(1, 4, 256), 256>>>(sc, vt, nullptr, cc, NS, NDK, NS,
                                      (long)NS * NS, (long)NS * NDK, 0,
                                      4, 1.f, nullptr);
    // out projection + row mask
    gemm_tn<<<dim3(4, 128, 1), 256>>>(cc, wo, bo, oo, M, ND, ND, 0, 0, 0, 5, 1.f, masks);
    // residual + LN2 -> final outputs
    ln_kernel<<<M, 128>>>(ln1, oo, ln2_g, ln2_b, out);
}

// round 4
// speedup vs baseline: 1.5308x; 1.5308x over previous
#include <cuda_runtime.h>
#include <cstdint>
#include <cstddef>

#define NB   32
#define NS   512
#define ND   512
#define NH2  256
#define NG3  768
#define NDK  64

// ------------------------- scratch (device globals) -------------------------
__device__ float g_xg[(size_t)2 * NB * NS * NG3];   // gate preactivations, per dir
__device__ float g_gru[(size_t)NB * NS * ND];       // concat GRU outputs
__device__ float g_ln1[(size_t)NB * NS * ND];       // ln1("outputs")
__device__ float g_q [(size_t)NB * 8 * NS * NDK];   // (b,h,s,d)
__device__ float g_k [(size_t)NB * 8 * NS * NDK];   // (b,h,s,d)
__device__ float g_vt[(size_t)NB * 8 * NDK * NS];   // (b,h,d,s)
__device__ float g_sc[(size_t)NB * 8 * NS * NS];    // scores -> p
__device__ float g_cc[(size_t)NB * NS * ND];        // attn concat
__device__ float g_o [(size_t)NB * NS * ND];        // out projection
__device__ float g_hx[16 * 2048];                   // h exchange (16 groups x 2 bufs x 1024)
__device__ unsigned g_flag[16 * 8 * 32];            // per (group,rank) step flag, 1 per 128B line

// ------------------------- f32x2 helpers -------------------------
__device__ __forceinline__ unsigned long long fma2(unsigned long long a,
                                                   unsigned long long b,
                                                   unsigned long long c) {
    unsigned long long d;
    asm("fma.rn.f32x2 %0, %1, %2, %3;" : "=l"(d) : "l"(a), "l"(b), "l"(c));
    return d;
}
__device__ __forceinline__ unsigned long long pack2(float x, float y) {
    unsigned long long d;
    asm("mov.b64 %0, {%1, %2};" : "=l"(d) : "f"(x), "f"(y));
    return d;
}
__device__ __forceinline__ void unpack2(unsigned long long v, float& x, float& y) {
    asm("mov.b64 {%0, %1}, %2;" : "=f"(x), "=f"(y) : "l"(v));
}

// ------------------------- generic TN GEMM -------------------------
// C = epi(A[M,K] @ W[N,K]^T). modes:
// 0: +bias              1: +bias, scatter (b,h,s,d)   2: +bias, scatter (b,h,d,s)
// 3: *scale             4: scatter concat (b,s,h*64+d) 5: +bias, *rowmask(masks)
__device__ __forceinline__ void store_elem(float* C, const float* bias,
                                           const int* masks, int mode, float scale,
                                           int z, int N, int mrow, int nc, float v) {
    if (nc >= N) return;
    if (mode == 0) {
        C[(long)mrow * N + nc] = v + bias[nc];
    } else if (mode == 1) {
        int b = mrow >> 9, s = mrow & 511, h = nc >> 6, d = nc & 63;
        C[(((long)(b * 8 + h) * NS + s)) * NDK + d] = v + bias[nc];
    } else if (mode == 2) {
        int b = mrow >> 9, s = mrow & 511, h = nc >> 6, d = nc & 63;
        C[((long)(b * 8 + h) * NDK + d) * NS + s] = v + bias[nc];
    } else if (mode == 3) {
        C[(long)mrow * N + nc] = v * scale;
    } else if (mode == 4) {
        int b = z >> 3, h = z & 7;
        C[((long)(b * NS + mrow)) * ND + h * NDK + nc] = v;
    } else {
        C[(long)mrow * N + nc] = masks[mrow] ? (v + bias[nc]) : 0.f;
    }
}

__global__ void __launch_bounds__(256) gemm_tn(
    const float* __restrict__ A, const float* __restrict__ W,
    const float* __restrict__ bias, float* __restrict__ C,
    int M, int N, int K, long sA, long sW, long sC,
    int mode, float scale, const int* __restrict__ masks)
{
    __shared__ float As[8][128];
    __shared__ float Ws[8][128];

    const int z = blockIdx.z;
    A += (long)z * sA;
    W += (long)z * sW;
    if (mode == 0 || mode == 3) C += (long)z * sC;

    const int m0 = blockIdx.y * 128, n0 = blockIdx.x * 128;
    const int tid = threadIdx.x;
    const int lrow = tid >> 1, lkq = tid & 1;
    const int tx = tid & 15, ty = tid >> 4;
    const bool wok = (n0 + lrow) < N;
    const float* Ap = A + (long)(m0 + lrow) * K + lkq * 4;
    const float* Wp = W + (long)(n0 + lrow) * K + lkq * 4;

    unsigned long long acc[8][4];
#pragma unroll
    for (int i = 0; i < 8; i++) {
        acc[i][0] = 0ull; acc[i][1] = 0ull; acc[i][2] = 0ull; acc[i][3] = 0ull;
    }

    float4 av = *(const float4*)Ap;
    float4 wv = wok ? *(const float4*)Wp : make_float4(0.f, 0.f, 0.f, 0.f);

    for (int k0 = 0; k0 < K; k0 += 8) {
        __syncthreads();
        As[lkq * 4 + 0][lrow] = av.x; As[lkq * 4 + 1][lrow] = av.y;
        As[lkq * 4 + 2][lrow] = av.z; As[lkq * 4 + 3][lrow] = av.w;
        Ws[lkq * 4 + 0][lrow] = wv.x; Ws[lkq * 4 + 1][lrow] = wv.y;
        Ws[lkq * 4 + 2][lrow] = wv.z; Ws[lkq * 4 + 3][lrow] = wv.w;
        __syncthreads();
        if (k0 + 8 < K) {
            av = *(const float4*)(Ap + k0 + 8);
            wv = wok ? *(const float4*)(Wp + k0 + 8) : make_float4(0.f, 0.f, 0.f, 0.f);
        }
#pragma unroll
        for (int kk = 0; kk < 8; kk++) {
            float4 a0 = *(const float4*)&As[kk][ty * 4];
            float4 a1 = *(const float4*)&As[kk][ty * 4 + 64];
            ulonglong2 w0 = *(const ulonglong2*)&Ws[kk][tx * 4];
            ulonglong2 w1 = *(const ulonglong2*)&Ws[kk][tx * 4 + 64];
            unsigned long long ap[8];
            ap[0] = pack2(a0.x, a0.x); ap[1] = pack2(a0.y, a0.y);
            ap[2] = pack2(a0.z, a0.z); ap[3] = pack2(a0.w, a0.w);
            ap[4] = pack2(a1.x, a1.x); ap[5] = pack2(a1.y, a1.y);
            ap[6] = pack2(a1.z, a1.z); ap[7] = pack2(a1.w, a1.w);
#pragma unroll
            for (int i = 0; i < 8; i++) {
                acc[i][0] = fma2(ap[i], w0.x, acc[i][0]);
                acc[i][1] = fma2(ap[i], w0.y, acc[i][1]);
                acc[i][2] = fma2(ap[i], w1.x, acc[i][2]);
                acc[i][3] = fma2(ap[i], w1.y, acc[i][3]);
            }
        }
    }

#pragma unroll
    for (int i = 0; i < 8; i++) {
        int mrow = m0 + ty * 4 + (i & 3) + (i >> 2) * 64;
#pragma unroll
        for (int jp = 0; jp < 4; jp++) {
            float lo, hi;
            unpack2(acc[i][jp], lo, hi);
            int nc = n0 + tx * 4 + (jp & 1) * 2 + (jp >> 1) * 64;
            store_elem(C, bias, masks, mode, scale, z, N, mrow, nc, lo);
            store_elem(C, bias, masks, mode, scale, z, N, mrow, nc + 1, hi);
        }
    }
}

// ------------------------- flag reset -------------------------
__global__ void reset_kernel() {
    g_flag[blockIdx.x * 256 + threadIdx.x] = 0u;
}

// ------------------------- persistent GRU -------------------------
// 128 blocks = dir(2) x batchgroup(8 of 4 batches) x jchunk(8 of 32 j).
// 384 threads: (r in [0,96)) x (kq in [0,4)); recurrent weights register-resident.
// h exchanged across the 8 j-chunk blocks of a group via L2 (st.cg) with
// per-rank release flags (one per 128B line); tight acquire spin, no atomics.
__global__ void __launch_bounds__(384, 1) gru_kernel(
    const float* __restrict__ whf, const float* __restrict__ whb,
    const float* __restrict__ bhf, const float* __restrict__ bhb,
    const int* __restrict__ masks, float* __restrict__ hid_out)
{
    __shared__ float sh_h[1024];     // [b][k] full h for 4 batches
    __shared__ float sh_part[1536];  // [r][b][kq]
    __shared__ float sh_gate[384];   // [r][b]

    const int bid = blockIdx.x;
    const int dir = bid >> 6;
    const int rem = bid & 63;
    const int bg  = rem >> 3;
    const int jc  = rem & 7;
    const int grp = dir * 8 + bg;
    const int tid = threadIdx.x;
    const int r   = tid >> 2;        // 0..95 (gate-row in block)
    const int kq  = tid & 3;         // k quarter
    const int G   = (r >> 5) * 256 + jc * 32 + (r & 31);

    const float* wh = dir ? whb : whf;
    const float* bh = dir ? bhb : bhf;
    const float bhh = bh[G];

    unsigned long long wp[32];
    {
        const float* ws = wh + (long)G * NH2 + kq * 64;
#pragma unroll
        for (int i = 0; i < 32; i++) wp[i] = pack2(ws[2 * i], ws[2 * i + 1]);
    }

    const int ju = tid & 31, bu = tid >> 5;   // updater role (tid < 128)
    const int jglob = jc * 32 + ju;
    const int bglob = bg * 4 + bu;
    const float* xgp = g_xg + ((size_t)dir * NB + bglob) * NS * NG3;
    float* hxg = g_hx + grp * 2048;
    unsigned* myflag = &g_flag[(grp * 8 + jc) * 32];

    for (int i = tid; i < 1024; i += 384) sh_h[i] = 0.f;
    float hreg = 0.f;
    __syncthreads();

    for (int t = 0; t < NS; t++) {
        const int s = dir ? (NS - 1 - t) : t;
        float xr = 0.f, xz = 0.f, xn = 0.f;
        int mk = 0;
        if (tid < 128) {  // prefetch x-gates + mask (independent of h)
            const float* xrow = xgp + (size_t)s * NG3;
            xr = __ldg(xrow + jglob);
            xz = __ldg(xrow + NH2 + jglob);
            xn = __ldg(xrow + 2 * NH2 + jglob);
            mk = __ldg(masks + bglob * NS + s);
        }
        if (t > 0) {
            if (tid < 8) {  // one spinner per producer rank, distinct L2 lines
                const unsigned* fp = &g_flag[(grp * 8 + tid) * 32];
                unsigned v;
                do {
                    asm volatile("ld.global.acquire.gpu.u32 %0, [%1];"
                                 : "=r"(v) : "l"(fp) : "memory");
                } while (v < (unsigned)t);
                __threadfence();
            }
            __syncthreads();
            const float4* src = (const float4*)(hxg + ((t - 1) & 1) * 1024);
            if (tid < 256) {
                float4 hv4;
                asm volatile("ld.global.cg.v4.f32 {%0,%1,%2,%3}, [%4];"
                             : "=f"(hv4.x), "=f"(hv4.y), "=f"(hv4.z), "=f"(hv4.w)
                             : "l"(src + tid) : "memory");
                *(float4*)&sh_h[tid * 4] = hv4;
            }
            __syncthreads();
        }
        // hg partial dot products (f32x2)
        unsigned long long acc[4] = {0ull, 0ull, 0ull, 0ull};
#pragma unroll
        for (int i = 0; i < 16; i++) {
#pragma unroll
            for (int b = 0; b < 4; b++) {
                ulonglong2 hv = *(const ulonglong2*)(sh_h + b * 256 + kq * 64 + i * 4);
                acc[b] = fma2(wp[2 * i],     hv.x, acc[b]);
                acc[b] = fma2(wp[2 * i + 1], hv.y, acc[b]);
            }
        }
#pragma unroll
        for (int b = 0; b < 4; b++) {
            float lo, hi;
            unpack2(acc[b], lo, hi);
            sh_part[r * 16 + b * 4 + kq] = lo + hi;
        }
        __syncthreads();
        {   // k-quarter reduction: thread -> (r, b2=kq)
            const int base = r * 16 + kq * 4;
            sh_gate[r * 4 + kq] = sh_part[base] + sh_part[base + 1] +
                                  sh_part[base + 2] + sh_part[base + 3] + bhh;
        }
        __syncthreads();
        if (tid < 128) {
            const float hgr = sh_gate[ju * 4 + bu];
            const float hgz = sh_gate[(32 + ju) * 4 + bu];
            const float hgn = sh_gate[(64 + ju) * 4 + bu];
            const float rr = 1.f / (1.f + __expf(-(xr + hgr)));
            const float zz = 1.f / (1.f + __expf(-(xz + hgz)));
            const float na = xn + rr * hgn;
            const float nn = 2.f / (1.f + __expf(-2.f * na)) - 1.f;  // tanh
            const float hnew = (1.f - zz) * nn + zz * hreg;
            hreg = mk ? hnew : hreg;
            g_gru[((size_t)bglob * NS + s) * ND + dir * NH2 + jglob] = mk ? hreg : 0.f;
            if (t == NS - 1) {
                hid_out[bglob * ND + dir * NH2 + jglob] = hreg;
            } else {
                __stcg(hxg + (t & 1) * 1024 + bu * 256 + jglob, hreg);
            }
            __threadfence();
        }
        if (t < NS - 1) {
            __syncthreads();
            if (tid == 0) {
                unsigned nv = (unsigned)(t + 1);
                asm volatile("st.global.cg.u32 [%0], %1;"
                             :: "l"(myflag), "r"(nv) : "memory");
            }
        }
    }
}

// ------------------------- layernorm (optionally fused residual) -------------------------
__global__ void __launch_bounds__(128) ln_kernel(
    const float* __restrict__ x, const float* __restrict__ y,
    const float* __restrict__ gam, const float* __restrict__ bet,
    float* __restrict__ out)
{
    __shared__ float red[8];
    const int row = blockIdx.x;
    const int tid = threadIdx.x;
    float4 v = *(const float4*)(x + (size_t)row * ND + tid * 4);
    if (y) {
        float4 w = *(const float4*)(y + (size_t)row * ND + tid * 4);
        v.x += w.x; v.y += w.y; v.z += w.z; v.w += w.w;
    }
    float s1 = v.x + v.y + v.z + v.w;
    float s2 = v.x * v.x + v.y * v.y + v.z * v.z + v.w * v.w;
#pragma unroll
    for (int o = 16; o; o >>= 1) {
        s1 += __shfl_xor_sync(~0u, s1, o);
        s2 += __shfl_xor_sync(~0u, s2, o);
    }
    const int wid = tid >> 5;
    if ((tid & 31) == 0) { red[wid] = s1; red[wid + 4] = s2; }
    __syncthreads();
    s1 = red[0] + red[1] + red[2] + red[3];
    s2 = red[4] + red[5] + red[6] + red[7];
    const float mu = s1 * (1.f / ND);
    const float var = s2 * (1.f / ND) - mu * mu;
    const float rs = rsqrtf(var + 1e-5f);
    const float4 gv = *(const float4*)(gam + tid * 4);
    const float4 bv = *(const float4*)(bet + tid * 4);
    float4 o4;
    o4.x = (v.x - mu) * rs * gv.x + bv.x;
    o4.y = (v.y - mu) * rs * gv.y + bv.y;
    o4.z = (v.z - mu) * rs * gv.z + bv.z;
    o4.w = (v.w - mu) * rs * gv.w + bv.w;
    *(float4*)(out + (size_t)row * ND + tid * 4) = o4;
}

// ------------------------- masked prefix softmax -------------------------
__global__ void __launch_bounds__(128) softmax_kernel(
    float* __restrict__ P, const int* __restrict__ lengths)
{
    __shared__ float red[4];
    const int q = blockIdx.x, z = blockIdx.y;
    const int len = __ldg(lengths + (z >> 3));
    float* row = P + ((size_t)z * NS + q) * NS;
    const int tid = threadIdx.x;
    const int c0 = tid * 4;
    if (q >= len) {
        *(float4*)(row + c0) = make_float4(0.f, 0.f, 0.f, 0.f);
        return;
    }
    float4 v = *(const float4*)(row + c0);
    const bool b0 = c0 < len, b1 = c0 + 1 < len, b2 = c0 + 2 < len, b3 = c0 + 3 < len;
    float m = -1e30f;
    if (b0) m = fmaxf(m, v.x);
    if (b1) m = fmaxf(m, v.y);
    if (b2) m = fmaxf(m, v.z);
    if (b3) m = fmaxf(m, v.w);
#pragma unroll
    for (int o = 16; o; o >>= 1) m = fmaxf(m, __shfl_xor_sync(~0u, m, o));
    const int wid = tid >> 5;
    if ((tid & 31) == 0) red[wid] = m;
    __syncthreads();
    m = fmaxf(fmaxf(red[0], red[1]), fmaxf(red[2], red[3]));
    __syncthreads();
    float4 e;
    e.x = b0 ? __expf(v.x - m) : 0.f;
    e.y = b1 ? __expf(v.y - m) : 0.f;
    e.z = b2 ? __expf(v.z - m) : 0.f;
    e.w = b3 ? __expf(v.w - m) : 0.f;
    float s = e.x + e.y + e.z + e.w;
#pragma unroll
    for (int o = 16; o; o >>= 1) s += __shfl_xor_sync(~0u, s, o);
    if ((tid & 31) == 0) red[wid] = s;
    __syncthreads();
    s = red[0] + red[1] + red[2] + red[3];
    const float inv = 1.f / s;
    e.x *= inv; e.y *= inv; e.z *= inv; e.w *= inv;
    *(float4*)(row + c0) = e;
}

// ------------------------- launch -------------------------
extern "C" void kernel_launch(void* const* d_in, const int* in_sizes, int n_in,
                              void* d_out, int out_size)
{
    const float* splits = (const float*)d_in[0];
    const float* w_ih_f = (const float*)d_in[1];
    const float* w_hh_f = (const float*)d_in[2];
    const float* b_ih_f = (const float*)d_in[3];
    const float* b_hh_f = (const float*)d_in[4];
    const float* w_ih_b = (const float*)d_in[5];
    const float* w_hh_b = (const float*)d_in[6];
    const float* b_ih_b = (const float*)d_in[7];
    const float* b_hh_b = (const float*)d_in[8];
    const float* ln1_g  = (const float*)d_in[9];
    const float* ln1_b  = (const float*)d_in[10];
    const float* wq = (const float*)d_in[11];
    const float* bq = (const float*)d_in[12];
    const float* wk = (const float*)d_in[13];
    const float* bk = (const float*)d_in[14];
    const float* wv = (const float*)d_in[15];
    const float* bv = (const float*)d_in[16];
    const float* wo = (const float*)d_in[17];
    const float* bo = (const float*)d_in[18];
    const float* ln2_g = (const float*)d_in[19];
    const float* ln2_b = (const float*)d_in[20];
    const int* lengths = (const int*)d_in[21];
    const int* masks   = (const int*)d_in[22];
    float* out = (float*)d_out;

    float *xg, *gru, *ln1, *q, *k, *vt, *sc, *cc, *oo;
    cudaGetSymbolAddress((void**)&xg,  g_xg);
    cudaGetSymbolAddress((void**)&gru, g_gru);
    cudaGetSymbolAddress((void**)&ln1, g_ln1);
    cudaGetSymbolAddress((void**)&q,   g_q);
    cudaGetSymbolAddress((void**)&k,   g_k);
    cudaGetSymbolAddress((void**)&vt,  g_vt);
    cudaGetSymbolAddress((void**)&sc,  g_sc);
    cudaGetSymbolAddress((void**)&cc,  g_cc);
    cudaGetSymbolAddress((void**)&oo,  g_o);

    const int M = NB * NS;  // 16384

    // GRU input projections (both dirs)
    gemm_tn<<<dim3(6, 128, 1), 256>>>(splits, w_ih_f, b_ih_f, xg,
                                      M, NG3, ND, 0, 0, 0, 0, 1.f, nullptr);
    gemm_tn<<<dim3(6, 128, 1), 256>>>(splits, w_ih_b, b_ih_b, xg + (size_t)M * NG3,
                                      M, NG3, ND, 0, 0, 0, 0, 1.f, nullptr);
    // GRU recurrence (persistent, per-rank flag sync through L2)
    reset_kernel<<<16, 256>>>();
    gru_kernel<<<128, 384>>>(w_hh_f, w_hh_b, b_hh_f, b_hh_b, masks,
                             out + (size_t)NB * NS * ND);
    // LN1
    ln_kernel<<<M, 128>>>(gru, nullptr, ln1_g, ln1_b, ln1);
    // Q/K/V projections with head scatter
    gemm_tn<<<dim3(4, 128, 1), 256>>>(ln1, wq, bq, q,  M, ND, ND, 0, 0, 0, 1, 1.f, nullptr);
    gemm_tn<<<dim3(4, 128, 1), 256>>>(ln1, wk, bk, k,  M, ND, ND, 0, 0, 0, 1, 1.f, nullptr);
    gemm_tn<<<dim3(4, 128, 1), 256>>>(ln1, wv, bv, vt, M, ND, ND, 0, 0, 0, 2, 1.f, nullptr);
    // scores = q @ k^T / 8   (z = b*8+h)
    gemm_tn<<<dim3(4, 4, 256), 256>>>(q, k, nullptr, sc, NS, NS, NDK,
                                      (long)NS * NDK, (long)NS * NDK, (long)NS * NS,
                                      3, 0.125f, nullptr);
    // masked prefix softmax (in place)
    softmax_kernel<<<dim3(NS, 256), 128>>>(sc, lengths);
    // attn = p @ v  -> concat layout
    gemm_tn<<<dim3(1, 4, 256), 256>>>(sc, vt, nullptr, cc, NS, NDK, NS,
                                      (long)NS * NS, (long)NS * NDK, 0,
                                      4, 1.f, nullptr);
    // out projection + row mask
    gemm_tn<<<dim3(4, 128, 1), 256>>>(cc, wo, bo, oo, M, ND, ND, 0, 0, 0, 5, 1.f, masks);
    // residual + LN2 -> final outputs
    ln_kernel<<<M, 128>>>(ln1, oo, ln2_g, ln2_b, out);
}

// round 5
// speedup vs baseline: 2.4747x; 1.6166x over previous
#include <cuda_runtime.h>
#include <cstdint>
#include <cstddef>

#define NB   32
#define NS   512
#define ND   512
#define NH2  256
#define NG3  768
#define NDK  64

// ------------------------- scratch (device globals) -------------------------
__device__ float g_xg[(size_t)2 * NB * NS * NG3];   // gate preactivations, per dir
__device__ float g_gru[(size_t)NB * NS * ND];       // concat GRU outputs
__device__ float g_ln1[(size_t)NB * NS * ND];       // ln1("outputs")
__device__ float g_q [(size_t)NB * 8 * NS * NDK];   // (b,h,s,d)
__device__ float g_k [(size_t)NB * 8 * NS * NDK];   // (b,h,s,d)
__device__ float g_vt[(size_t)NB * 8 * NDK * NS];   // (b,h,d,s)
__device__ float g_sc[(size_t)NB * 8 * NS * NS];    // scores -> p
__device__ float g_cc[(size_t)NB * NS * ND];        // attn concat
__device__ float g_o [(size_t)NB * NS * ND];        // out projection
__device__ float g_hx[16 * 2048];                   // h exchange (16 groups x 2 bufs x 1024)
__device__ unsigned g_flag[16 * 8 * 32];            // per (group,rank) step flag, 1 per 128B line

// ------------------------- f32x2 helpers -------------------------
__device__ __forceinline__ unsigned long long fma2(unsigned long long a,
                                                   unsigned long long b,
                                                   unsigned long long c) {
    unsigned long long d;
    asm("fma.rn.f32x2 %0, %1, %2, %3;" : "=l"(d) : "l"(a), "l"(b), "l"(c));
    return d;
}
__device__ __forceinline__ unsigned long long pack2(float x, float y) {
    unsigned long long d;
    asm("mov.b64 %0, {%1, %2};" : "=l"(d) : "f"(x), "f"(y));
    return d;
}
__device__ __forceinline__ void unpack2(unsigned long long v, float& x, float& y) {
    asm("mov.b64 {%0, %1}, %2;" : "=f"(x), "=f"(y) : "l"(v));
}

// ------------------------- generic TN GEMM -------------------------
// C = epi(A[M,K] @ W[N,K]^T). modes:
// 0: +bias              1: +bias, scatter (b,h,s,d)   2: +bias, scatter (b,h,d,s)
// 3: *scale             4: scatter concat (b,s,h*64+d) 5: +bias, *rowmask(masks)
__device__ __forceinline__ void store_elem(float* C, const float* bias,
                                           const int* masks, int mode, float scale,
                                           int z, int N, int mrow, int nc, float v) {
    if (nc >= N) return;
    if (mode == 0) {
        C[(long)mrow * N + nc] = v + bias[nc];
    } else if (mode == 1) {
        int b = mrow >> 9, s = mrow & 511, h = nc >> 6, d = nc & 63;
        C[(((long)(b * 8 + h) * NS + s)) * NDK + d] = v + bias[nc];
    } else if (mode == 2) {
        int b = mrow >> 9, s = mrow & 511, h = nc >> 6, d = nc & 63;
        C[((long)(b * 8 + h) * NDK + d) * NS + s] = v + bias[nc];
    } else if (mode == 3) {
        C[(long)mrow * N + nc] = v * scale;
    } else if (mode == 4) {
        int b = z >> 3, h = z & 7;
        C[((long)(b * NS + mrow)) * ND + h * NDK + nc] = v;
    } else {
        C[(long)mrow * N + nc] = masks[mrow] ? (v + bias[nc]) : 0.f;
    }
}

__global__ void __launch_bounds__(256) gemm_tn(
    const float* __restrict__ A, const float* __restrict__ W,
    const float* __restrict__ bias, float* __restrict__ C,
    int M, int N, int K, long sA, long sW, long sC,
    int mode, float scale, const int* __restrict__ masks)
{
    __shared__ float As[8][128];
    __shared__ float Ws[8][128];

    const int z = blockIdx.z;
    A += (long)z * sA;
    W += (long)z * sW;
    if (mode == 0 || mode == 3) C += (long)z * sC;

    const int m0 = blockIdx.y * 128, n0 = blockIdx.x * 128;
    const int tid = threadIdx.x;
    const int lrow = tid >> 1, lkq = tid & 1;
    const int tx = tid & 15, ty = tid >> 4;
    const bool wok = (n0 + lrow) < N;
    const float* Ap = A + (long)(m0 + lrow) * K + lkq * 4;
    const float* Wp = W + (long)(n0 + lrow) * K + lkq * 4;

    unsigned long long acc[8][4];
#pragma unroll
    for (int i = 0; i < 8; i++) {
        acc[i][0] = 0ull; acc[i][1] = 0ull; acc[i][2] = 0ull; acc[i][3] = 0ull;
    }

    float4 av = *(const float4*)Ap;
    float4 wv = wok ? *(const float4*)Wp : make_float4(0.f, 0.f, 0.f, 0.f);

    for (int k0 = 0; k0 < K; k0 += 8) {
        __syncthreads();
        As[lkq * 4 + 0][lrow] = av.x; As[lkq * 4 + 1][lrow] = av.y;
        As[lkq * 4 + 2][lrow] = av.z; As[lkq * 4 + 3][lrow] = av.w;
        Ws[lkq * 4 + 0][lrow] = wv.x; Ws[lkq * 4 + 1][lrow] = wv.y;
        Ws[lkq * 4 + 2][lrow] = wv.z; Ws[lkq * 4 + 3][lrow] = wv.w;
        __syncthreads();
        if (k0 + 8 < K) {
            av = *(const float4*)(Ap + k0 + 8);
            wv = wok ? *(const float4*)(Wp + k0 + 8) : make_float4(0.f, 0.f, 0.f, 0.f);
        }
#pragma unroll
        for (int kk = 0; kk < 8; kk++) {
            float4 a0 = *(const float4*)&As[kk][ty * 4];
            float4 a1 = *(const float4*)&As[kk][ty * 4 + 64];
            ulonglong2 w0 = *(const ulonglong2*)&Ws[kk][tx * 4];
            ulonglong2 w1 = *(const ulonglong2*)&Ws[kk][tx * 4 + 64];
            unsigned long long ap[8];
            ap[0] = pack2(a0.x, a0.x); ap[1] = pack2(a0.y, a0.y);
            ap[2] = pack2(a0.z, a0.z); ap[3] = pack2(a0.w, a0.w);
            ap[4] = pack2(a1.x, a1.x); ap[5] = pack2(a1.y, a1.y);
            ap[6] = pack2(a1.z, a1.z); ap[7] = pack2(a1.w, a1.w);
#pragma unroll
            for (int i = 0; i < 8; i++) {
                acc[i][0] = fma2(ap[i], w0.x, acc[i][0]);
                acc[i][1] = fma2(ap[i], w0.y, acc[i][1]);
                acc[i][2] = fma2(ap[i], w1.x, acc[i][2]);
                acc[i][3] = fma2(ap[i], w1.y, acc[i][3]);
            }
        }
    }

#pragma unroll
    for (int i = 0; i < 8; i++) {
        int mrow = m0 + ty * 4 + (i & 3) + (i >> 2) * 64;
#pragma unroll
        for (int jp = 0; jp < 4; jp++) {
            float lo, hi;
            unpack2(acc[i][jp], lo, hi);
            int nc = n0 + tx * 4 + (jp & 1) * 2 + (jp >> 1) * 64;
            store_elem(C, bias, masks, mode, scale, z, N, mrow, nc, lo);
            store_elem(C, bias, masks, mode, scale, z, N, mrow, nc + 1, hi);
        }
    }
}

// ------------------------- flag reset -------------------------
__global__ void reset_kernel() {
    g_flag[blockIdx.x * 256 + threadIdx.x] = 0u;
}

// ------------------------- persistent GRU -------------------------
// 128 blocks = dir(2) x batchgroup(8 of 4 batches) x jchunk(8 of 32 j).
// 384 threads: (r in [0,96)) x (kq in [0,4)); recurrent weights register-resident.
// h exchanged across the 8 j-chunk blocks of a group via L2 (st.cg) with
// per-rank release flags; h held in smem with an XOR swizzle so the 4
// kq-quarters of a warp read disjoint bank groups (conflict-free broadcast).
//
// swizzle: logical 16B chunk c (kq=c>>4, i=c&15) of batch b lives at
//          physical chunk (kq<<4)|(i^kq) of batch b.
__global__ void __launch_bounds__(384, 1) gru_kernel(
    const float* __restrict__ whf, const float* __restrict__ whb,
    const float* __restrict__ bhf, const float* __restrict__ bhb,
    const int* __restrict__ masks, float* __restrict__ hid_out)
{
    __shared__ float sh_h[1024];     // [b][swizzled k] h for 4 batches
    __shared__ float sh_part[1536];  // [r][b][kq]
    __shared__ float sh_gate[384];   // [r][b]

    const int bid = blockIdx.x;
    const int dir = bid >> 6;
    const int rem = bid & 63;
    const int bg  = rem >> 3;
    const int jc  = rem & 7;
    const int grp = dir * 8 + bg;
    const int tid = threadIdx.x;
    const int r   = tid >> 2;        // 0..95 (gate-row in block)
    const int kq  = tid & 3;         // k quarter
    const int G   = (r >> 5) * 256 + jc * 32 + (r & 31);

    const float* wh = dir ? whb : whf;
    const float* bh = dir ? bhb : bhf;
    const float bhh = bh[G];

    unsigned long long wp[32];
    {
        const float* ws = wh + (long)G * NH2 + kq * 64;
#pragma unroll
        for (int i = 0; i < 32; i++) wp[i] = pack2(ws[2 * i], ws[2 * i + 1]);
    }

    const int ju = tid & 31, bu = tid >> 5;   // updater role (tid < 128)
    const int jglob = jc * 32 + ju;
    const int bglob = bg * 4 + bu;
    const float* xgp = g_xg + ((size_t)dir * NB + bglob) * NS * NG3;
    float* hxg = g_hx + grp * 2048;
    unsigned* myflag = &g_flag[(grp * 8 + jc) * 32];

    // consumer-copy swizzled destination for this thread (tid<256)
    const int cb = tid >> 6, cc0 = tid & 63;
    const int csw = ((cc0 >> 4) << 4) | ((cc0 & 15) ^ (cc0 >> 4));
    float* shdst = &sh_h[cb * 256 + csw * 4];

    for (int i = tid; i < 1024; i += 384) sh_h[i] = 0.f;
    float hreg = 0.f;
    __syncthreads();

    for (int t = 0; t < NS; t++) {
        const int s = dir ? (NS - 1 - t) : t;
        float xr = 0.f, xz = 0.f, xn = 0.f;
        int mk = 0;
        if (tid < 128) {  // prefetch x-gates + mask (independent of h)
            const float* xrow = xgp + (size_t)s * NG3;
            xr = __ldg(xrow + jglob);
            xz = __ldg(xrow + NH2 + jglob);
            xn = __ldg(xrow + 2 * NH2 + jglob);
            mk = __ldg(masks + bglob * NS + s);
        }
        if (t > 0) {
            if (tid < 8) {  // one spinner per producer rank, distinct L2 lines
                const unsigned* fp = &g_flag[(grp * 8 + tid) * 32];
                unsigned v;
                do {
                    asm volatile("ld.global.acquire.gpu.u32 %0, [%1];"
                                 : "=r"(v) : "l"(fp) : "memory");
                } while (v < (unsigned)t);
            }
            __syncthreads();
            if (tid < 256) {
                const float4* src = (const float4*)(hxg + ((t - 1) & 1) * 1024);
                float4 hv4;
                asm volatile("ld.global.cg.v4.f32 {%0,%1,%2,%3}, [%4];"
                             : "=f"(hv4.x), "=f"(hv4.y), "=f"(hv4.z), "=f"(hv4.w)
                             : "l"(src + tid) : "memory");
                *(float4*)shdst = hv4;
            }
            __syncthreads();
        }
        // hg partial dot products (f32x2), swizzle-aware, conflict-free
        unsigned long long acc[4] = {0ull, 0ull, 0ull, 0ull};
#pragma unroll
        for (int i = 0; i < 16; i++) {
            const int coff = ((kq << 4) | (i ^ kq)) * 4;
#pragma unroll
            for (int b = 0; b < 4; b++) {
                ulonglong2 hv = *(const ulonglong2*)(sh_h + b * 256 + coff);
                acc[b] = fma2(wp[2 * i],     hv.x, acc[b]);
                acc[b] = fma2(wp[2 * i + 1], hv.y, acc[b]);
            }
        }
#pragma unroll
        for (int b = 0; b < 4; b++) {
            float lo, hi;
            unpack2(acc[b], lo, hi);
            sh_part[r * 16 + b * 4 + kq] = lo + hi;
        }
        __syncthreads();
        {   // k-quarter reduction: thread -> (r, b2=kq)
            const int base = r * 16 + kq * 4;
            sh_gate[r * 4 + kq] = sh_part[base] + sh_part[base + 1] +
                                  sh_part[base + 2] + sh_part[base + 3] + bhh;
        }
        __syncthreads();
        if (tid < 128) {
            const float hgr = sh_gate[ju * 4 + bu];
            const float hgz = sh_gate[(32 + ju) * 4 + bu];
            const float hgn = sh_gate[(64 + ju) * 4 + bu];
            const float rr = 1.f / (1.f + __expf(-(xr + hgr)));
            const float zz = 1.f / (1.f + __expf(-(xz + hgz)));
            const float na = xn + rr * hgn;
            const float nn = 2.f / (1.f + __expf(-2.f * na)) - 1.f;  // tanh
            const float hnew = (1.f - zz) * nn + zz * hreg;
            hreg = mk ? hnew : hreg;
            g_gru[((size_t)bglob * NS + s) * ND + dir * NH2 + jglob] = mk ? hreg : 0.f;
            if (t == NS - 1) {
                hid_out[bglob * ND + dir * NH2 + jglob] = hreg;
            } else {
                __stcg(hxg + (t & 1) * 1024 + bu * 256 + jglob, hreg);
            }
        }
        if (t < NS - 1) {
            __syncthreads();     // all h stores program-ordered before here
            if (tid == 0) {
                __threadfence();  // cumulative: orders the block's stores gpu-wide
                unsigned nv = (unsigned)(t + 1);
                asm volatile("st.global.cg.u32 [%0], %1;"
                             :: "l"(myflag), "r"(nv) : "memory");
            }
        }
    }
}

// ------------------------- layernorm (optionally fused residual) -------------------------
__global__ void __launch_bounds__(128) ln_kernel(
    const float* __restrict__ x, const float* __restrict__ y,
    const float* __restrict__ gam, const float* __restrict__ bet,
    float* __restrict__ out)
{
    __shared__ float red[8];
    const int row = blockIdx.x;
    const int tid = threadIdx.x;
    float4 v = *(const float4*)(x + (size_t)row * ND + tid * 4);
    if (y) {
        float4 w = *(const float4*)(y + (size_t)row * ND + tid * 4);
        v.x += w.x; v.y += w.y; v.z += w.z; v.w += w.w;
    }
    float s1 = v.x + v.y + v.z + v.w;
    float s2 = v.x * v.x + v.y * v.y + v.z * v.z + v.w * v.w;
#pragma unroll
    for (int o = 16; o; o >>= 1) {
        s1 += __shfl_xor_sync(~0u, s1, o);
        s2 += __shfl_xor_sync(~0u, s2, o);
    }
    const int wid = tid >> 5;
    if ((tid & 31) == 0) { red[wid] = s1; red[wid + 4] = s2; }
    __syncthreads();
    s1 = red[0] + red[1] + red[2] + red[3];
    s2 = red[4] + red[5] + red[6] + red[7];
    const float mu = s1 * (1.f / ND);
    const float var = s2 * (1.f / ND) - mu * mu;
    const float rs = rsqrtf(var + 1e-5f);
    const float4 gv = *(const float4*)(gam + tid * 4);
    const float4 bv = *(const float4*)(bet + tid * 4);
    float4 o4;
    o4.x = (v.x - mu) * rs * gv.x + bv.x;
    o4.y = (v.y - mu) * rs * gv.y + bv.y;
    o4.z = (v.z - mu) * rs * gv.z + bv.z;
    o4.w = (v.w - mu) * rs * gv.w + bv.w;
    *(float4*)(out + (size_t)row * ND + tid * 4) = o4;
}

// ------------------------- masked prefix softmax -------------------------
__global__ void __launch_bounds__(128) softmax_kernel(
    float* __restrict__ P, const int* __restrict__ lengths)
{
    __shared__ float red[4];
    const int q = blockIdx.x, z = blockIdx.y;
    const int len = __ldg(lengths + (z >> 3));
    float* row = P + ((size_t)z * NS + q) * NS;
    const int tid = threadIdx.x;
    const int c0 = tid * 4;
    if (q >= len) {
        *(float4*)(row + c0) = make_float4(0.f, 0.f, 0.f, 0.f);
        return;
    }
    float4 v = *(const float4*)(row + c0);
    const bool b0 = c0 < len, b1 = c0 + 1 < len, b2 = c0 + 2 < len, b3 = c0 + 3 < len;
    float m = -1e30f;
    if (b0) m = fmaxf(m, v.x);
    if (b1) m = fmaxf(m, v.y);
    if (b2) m = fmaxf(m, v.z);
    if (b3) m = fmaxf(m, v.w);
#pragma unroll
    for (int o = 16; o; o >>= 1) m = fmaxf(m, __shfl_xor_sync(~0u, m, o));
    const int wid = tid >> 5;
    if ((tid & 31) == 0) red[wid] = m;
    __syncthreads();
    m = fmaxf(fmaxf(red[0], red[1]), fmaxf(red[2], red[3]));
    __syncthreads();
    float4 e;
    e.x = b0 ? __expf(v.x - m) : 0.f;
    e.y = b1 ? __expf(v.y - m) : 0.f;
    e.z = b2 ? __expf(v.z - m) : 0.f;
    e.w = b3 ? __expf(v.w - m) : 0.f;
    float s = e.x + e.y + e.z + e.w;
#pragma unroll
    for (int o = 16; o; o >>= 1) s += __shfl_xor_sync(~0u, s, o);
    if ((tid & 31) == 0) red[wid] = s;
    __syncthreads();
    s = red[0] + red[1] + red[2] + red[3];
    const float inv = 1.f / s;
    e.x *= inv; e.y *= inv; e.z *= inv; e.w *= inv;
    *(float4*)(row + c0) = e;
}

// ------------------------- launch -------------------------
extern "C" void kernel_launch(void* const* d_in, const int* in_sizes, int n_in,
                              void* d_out, int out_size)
{
    const float* splits = (const float*)d_in[0];
    const float* w_ih_f = (const float*)d_in[1];
    const float* w_hh_f = (const float*)d_in[2];
    const float* b_ih_f = (const float*)d_in[3];
    const float* b_hh_f = (const float*)d_in[4];
    const float* w_ih_b = (const float*)d_in[5];
    const float* w_hh_b = (const float*)d_in[6];
    const float* b_ih_b = (const float*)d_in[7];
    const float* b_hh_b = (const float*)d_in[8];
    const float* ln1_g  = (const float*)d_in[9];
    const float* ln1_b  = (const float*)d_in[10];
    const float* wq = (const float*)d_in[11];
    const float* bq = (const float*)d_in[12];
    const float* wk = (const float*)d_in[13];
    const float* bk = (const float*)d_in[14];
    const float* wv = (const float*)d_in[15];
    const float* bv = (const float*)d_in[16];
    const float* wo = (const float*)d_in[17];
    const float* bo = (const float*)d_in[18];
    const float* ln2_g = (const float*)d_in[19];
    const float* ln2_b = (const float*)d_in[20];
    const int* lengths = (const int*)d_in[21];
    const int* masks   = (const int*)d_in[22];
    float* out = (float*)d_out;

    float *xg, *gru, *ln1, *q, *k, *vt, *sc, *cc, *oo;
    cudaGetSymbolAddress((void**)&xg,  g_xg);
    cudaGetSymbolAddress((void**)&gru, g_gru);
    cudaGetSymbolAddress((void**)&ln1, g_ln1);
    cudaGetSymbolAddress((void**)&q,   g_q);
    cudaGetSymbolAddress((void**)&k,   g_k);
    cudaGetSymbolAddress((void**)&vt,  g_vt);
    cudaGetSymbolAddress((void**)&sc,  g_sc);
    cudaGetSymbolAddress((void**)&cc,  g_cc);
    cudaGetSymbolAddress((void**)&oo,  g_o);

    const int M = NB * NS;  // 16384

    // GRU input projections (both dirs)
    gemm_tn<<<dim3(6, 128, 1), 256>>>(splits, w_ih_f, b_ih_f, xg,
                                      M, NG3, ND, 0, 0, 0, 0, 1.f, nullptr);
    gemm_tn<<<dim3(6, 128, 1), 256>>>(splits, w_ih_b, b_ih_b, xg + (size_t)M * NG3,
                                      M, NG3, ND, 0, 0, 0, 0, 1.f, nullptr);
    // GRU recurrence (persistent, per-rank flag sync through L2)
    reset_kernel<<<16, 256>>>();
    gru_kernel<<<128, 384>>>(w_hh_f, w_hh_b, b_hh_f, b_hh_b, masks,
                             out + (size_t)NB * NS * ND);
    // LN1
    ln_kernel<<<M, 128>>>(gru, nullptr, ln1_g, ln1_b, ln1);
    // Q/K/V projections with head scatter
    gemm_tn<<<dim3(4, 128, 1), 256>>>(ln1, wq, bq, q,  M, ND, ND, 0, 0, 0, 1, 1.f, nullptr);
    gemm_tn<<<dim3(4, 128, 1), 256>>>(ln1, wk, bk, k,  M, ND, ND, 0, 0, 0, 1, 1.f, nullptr);
    gemm_tn<<<dim3(4, 128, 1), 256>>>(ln1, wv, bv, vt, M, ND, ND, 0, 0, 0, 2, 1.f, nullptr);
    // scores = q @ k^T / 8   (z = b*8+h)
    gemm_tn<<<dim3(4, 4, 256), 256>>>(q, k, nullptr, sc, NS, NS, NDK,
                                      (long)NS * NDK, (long)NS * NDK, (long)NS * NS,
                                      3, 0.125f, nullptr);
    // masked prefix softmax (in place)
    softmax_kernel<<<dim3(NS, 256), 128>>>(sc, lengths);
    // attn = p @ v  -> concat layout
    gemm_tn<<<dim3(1, 4, 256), 256>>>(sc, vt, nullptr, cc, NS, NDK, NS,
                                      (long)NS * NS, (long)NS * NDK, 0,
                                      4, 1.f, nullptr);
    // out projection + row mask
    gemm_tn<<<dim3(4, 128, 1), 256>>>(cc, wo, bo, oo, M, ND, ND, 0, 0, 0, 5, 1.f, masks);
    // residual + LN2 -> final outputs
    ln_kernel<<<M, 128>>>(ln1, oo, ln2_g, ln2_b, out);
}

// round 6
// speedup vs baseline: 3.1218x; 1.2615x over previous
#include <cuda_runtime.h>
#include <cstdint>
#include <cstddef>

#define NB   32
#define NS   512
#define ND   512
#define NH2  256
#define NG3  768
#define NDK  64

// ------------------------- scratch (device globals) -------------------------
__device__ float g_xg[(size_t)2 * NB * NS * NG3];   // gate preactivations, per dir
__device__ float g_gru[(size_t)NB * NS * ND];       // concat GRU outputs
__device__ float g_ln1[(size_t)NB * NS * ND];       // ln1("outputs")
__device__ float g_q [(size_t)NB * 8 * NS * NDK];   // (b,h,s,d)
__device__ float g_k [(size_t)NB * 8 * NS * NDK];   // (b,h,s,d)
__device__ float g_vt[(size_t)NB * 8 * NDK * NS];   // (b,h,d,s)
__device__ float g_sc[(size_t)NB * 8 * NS * NS];    // scores -> p
__device__ float g_cc[(size_t)NB * NS * ND];        // attn concat
__device__ float g_o [(size_t)NB * NS * ND];        // out projection
__device__ float g_hx[16 * 2048];                   // h exchange (16 groups x 2 bufs x 1024)
__device__ unsigned g_flag[16 * 8 * 32];            // per (group,rank) step flag, 1 per 128B line

// ------------------------- f32x2 helpers -------------------------
__device__ __forceinline__ unsigned long long fma2(unsigned long long a,
                                                   unsigned long long b,
                                                   unsigned long long c) {
    unsigned long long d;
    asm("fma.rn.f32x2 %0, %1, %2, %3;" : "=l"(d) : "l"(a), "l"(b), "l"(c));
    return d;
}
__device__ __forceinline__ unsigned long long pack2(float x, float y) {
    unsigned long long d;
    asm("mov.b64 %0, {%1, %2};" : "=l"(d) : "f"(x), "f"(y));
    return d;
}
__device__ __forceinline__ void unpack2(unsigned long long v, float& x, float& y) {
    asm("mov.b64 {%0, %1}, %2;" : "=f"(x), "=f"(y) : "l"(v));
}
__device__ __forceinline__ float tf32r(float f) {
    unsigned u;
    asm("cvt.rna.tf32.f32 %0, %1;" : "=r"(u) : "f"(f));
    return __uint_as_float(u);
}

// ------------------------- epilogue store (shared by both GEMMs) -------------------------
// modes:
// 0: +bias              1: +bias, scatter (b,h,s,d)   2: +bias, scatter (b,h,d,s)
// 3: *scale             4: scatter concat (b,s,h*64+d) 5: +bias, *rowmask(masks)
__device__ __forceinline__ void store_elem(float* C, const float* bias,
                                           const int* masks, int mode, float scale,
                                           int z, int N, int mrow, int nc, float v) {
    if (nc >= N) return;
    if (mode == 0) {
        C[(long)mrow * N + nc] = v + bias[nc];
    } else if (mode == 1) {
        int b = mrow >> 9, s = mrow & 511, h = nc >> 6, d = nc & 63;
        C[(((long)(b * 8 + h) * NS + s)) * NDK + d] = v + bias[nc];
    } else if (mode == 2) {
        int b = mrow >> 9, s = mrow & 511, h = nc >> 6, d = nc & 63;
        C[((long)(b * 8 + h) * NDK + d) * NS + s] = v + bias[nc];
    } else if (mode == 3) {
        C[(long)mrow * N + nc] = v * scale;
    } else if (mode == 4) {
        int b = z >> 3, h = z & 7;
        C[((long)(b * NS + mrow)) * ND + h * NDK + nc] = v;
    } else {
        C[(long)mrow * N + nc] = masks[mrow] ? (v + bias[nc]) : 0.f;
    }
}

// ------------------------- fp32 f32x2 TN GEMM (kept for GRU input proj) -------------------------
__global__ void __launch_bounds__(256) gemm_tn(
    const float* __restrict__ A, const float* __restrict__ W,
    const float* __restrict__ bias, float* __restrict__ C,
    int M, int N, int K, long sA, long sW, long sC,
    int mode, float scale, const int* __restrict__ masks)
{
    __shared__ float As[8][128];
    __shared__ float Ws[8][128];

    const int z = blockIdx.z;
    A += (long)z * sA;
    W += (long)z * sW;
    if (mode == 0 || mode == 3) C += (long)z * sC;

    const int m0 = blockIdx.y * 128, n0 = blockIdx.x * 128;
    const int tid = threadIdx.x;
    const int lrow = tid >> 1, lkq = tid & 1;
    const int tx = tid & 15, ty = tid >> 4;
    const bool wok = (n0 + lrow) < N;
    const float* Ap = A + (long)(m0 + lrow) * K + lkq * 4;
    const float* Wp = W + (long)(n0 + lrow) * K + lkq * 4;

    unsigned long long acc[8][4];
#pragma unroll
    for (int i = 0; i < 8; i++) {
        acc[i][0] = 0ull; acc[i][1] = 0ull; acc[i][2] = 0ull; acc[i][3] = 0ull;
    }

    float4 av = *(const float4*)Ap;
    float4 wv = wok ? *(const float4*)Wp : make_float4(0.f, 0.f, 0.f, 0.f);

    for (int k0 = 0; k0 < K; k0 += 8) {
        __syncthreads();
        As[lkq * 4 + 0][lrow] = av.x; As[lkq * 4 + 1][lrow] = av.y;
        As[lkq * 4 + 2][lrow] = av.z; As[lkq * 4 + 3][lrow] = av.w;
        Ws[lkq * 4 + 0][lrow] = wv.x; Ws[lkq * 4 + 1][lrow] = wv.y;
        Ws[lkq * 4 + 2][lrow] = wv.z; Ws[lkq * 4 + 3][lrow] = wv.w;
        __syncthreads();
        if (k0 + 8 < K) {
            av = *(const float4*)(Ap + k0 + 8);
            wv = wok ? *(const float4*)(Wp + k0 + 8) : make_float4(0.f, 0.f, 0.f, 0.f);
        }
#pragma unroll
        for (int kk = 0; kk < 8; kk++) {
            float4 a0 = *(const float4*)&As[kk][ty * 4];
            float4 a1 = *(const float4*)&As[kk][ty * 4 + 64];
            ulonglong2 w0 = *(const ulonglong2*)&Ws[kk][tx * 4];
            ulonglong2 w1 = *(const ulonglong2*)&Ws[kk][tx * 4 + 64];
            unsigned long long ap[8];
            ap[0] = pack2(a0.x, a0.x); ap[1] = pack2(a0.y, a0.y);
            ap[2] = pack2(a0.z, a0.z); ap[3] = pack2(a0.w, a0.w);
            ap[4] = pack2(a1.x, a1.x); ap[5] = pack2(a1.y, a1.y);
            ap[6] = pack2(a1.z, a1.z); ap[7] = pack2(a1.w, a1.w);
#pragma unroll
            for (int i = 0; i < 8; i++) {
                acc[i][0] = fma2(ap[i], w0.x, acc[i][0]);
                acc[i][1] = fma2(ap[i], w0.y, acc[i][1]);
                acc[i][2] = fma2(ap[i], w1.x, acc[i][2]);
                acc[i][3] = fma2(ap[i], w1.y, acc[i][3]);
            }
        }
    }

#pragma unroll
    for (int i = 0; i < 8; i++) {
        int mrow = m0 + ty * 4 + (i & 3) + (i >> 2) * 64;
#pragma unroll
        for (int jp = 0; jp < 4; jp++) {
            float lo, hi;
            unpack2(acc[i][jp], lo, hi);
            int nc = n0 + tx * 4 + (jp & 1) * 2 + (jp >> 1) * 64;
            store_elem(C, bias, masks, mode, scale, z, N, mrow, nc, lo);
            store_elem(C, bias, masks, mode, scale, z, N, mrow, nc + 1, hi);
        }
    }
}

// ------------------------- tf32 tensor-core TN GEMM -------------------------
// C = epi(A[M,K] @ W[N,K]^T) via mma.sync.m16n8k8 tf32.
// 128x128x16 tile, 256 thr = 8 warps (2x4), each warp 64x32.
__global__ void __launch_bounds__(256) gemm_tf32(
    const float* __restrict__ A, const float* __restrict__ W,
    const float* __restrict__ bias, float* __restrict__ C,
    int M, int N, int K, long sA, long sW, long sC,
    int mode, float scale, const int* __restrict__ masks)
{
    __shared__ float As[128][20];   // [m][k], pad 20 -> conflict-free frag loads
    __shared__ float Ws[128][20];   // [n][k]

    const int z = blockIdx.z;
    A += (long)z * sA;
    W += (long)z * sW;
    if (mode == 3) C += (long)z * sC;

    const int m0 = blockIdx.y * 128, n0 = blockIdx.x * 128;
    const int tid  = threadIdx.x;
    const int warp = tid >> 5, lane = tid & 31;
    const int wm = warp >> 2, wn = warp & 3;   // warp grid 2 x 4
    const int g  = lane >> 2, tg = lane & 3;   // mma group / thread-in-group

    // loader coords: thread t covers rows lm, lm+64 at k chunk lkq*4
    const int lm = tid >> 2, lkq = tid & 3;
    const float* Aip = A + (long)(m0 + lm) * K + lkq * 4;
    const float* Wip = W + (long)(n0 + lm) * K + lkq * 4;
    const bool w0ok = (n0 + lm) < N;
    const bool w1ok = (n0 + lm + 64) < N;
    const float4 z4 = make_float4(0.f, 0.f, 0.f, 0.f);

    float acc[4][4][4];
#pragma unroll
    for (int mt = 0; mt < 4; mt++)
#pragma unroll
        for (int nt = 0; nt < 4; nt++)
#pragma unroll
            for (int c = 0; c < 4; c++) acc[mt][nt][c] = 0.f;

    float4 a0v = *(const float4*)Aip;
    float4 a1v = *(const float4*)(Aip + (long)64 * K);
    float4 w0v = w0ok ? *(const float4*)Wip : z4;
    float4 w1v = w1ok ? *(const float4*)(Wip + (long)64 * K) : z4;

    for (int k0 = 0; k0 < K; k0 += 16) {
        __syncthreads();
        {
            float* pa0 = &As[lm][lkq * 4];
            pa0[0] = tf32r(a0v.x); pa0[1] = tf32r(a0v.y);
            pa0[2] = tf32r(a0v.z); pa0[3] = tf32r(a0v.w);
            float* pa1 = &As[lm + 64][lkq * 4];
            pa1[0] = tf32r(a1v.x); pa1[1] = tf32r(a1v.y);
            pa1[2] = tf32r(a1v.z); pa1[3] = tf32r(a1v.w);
            float* pw0 = &Ws[lm][lkq * 4];
            pw0[0] = tf32r(w0v.x); pw0[1] = tf32r(w0v.y);
            pw0[2] = tf32r(w0v.z); pw0[3] = tf32r(w0v.w);
            float* pw1 = &Ws[lm + 64][lkq * 4];
            pw1[0] = tf32r(w1v.x); pw1[1] = tf32r(w1v.y);
            pw1[2] = tf32r(w1v.z); pw1[3] = tf32r(w1v.w);
        }
        __syncthreads();
        if (k0 + 16 < K) {
            a0v = *(const float4*)(Aip + k0 + 16);
            a1v = *(const float4*)(Aip + (long)64 * K + k0 + 16);
            w0v = w0ok ? *(const float4*)(Wip + k0 + 16) : z4;
            w1v = w1ok ? *(const float4*)(Wip + (long)64 * K + k0 + 16) : z4;
        }
#pragma unroll
        for (int kb = 0; kb < 2; kb++) {
            const int kk = kb * 8 + tg;
            unsigned a[4][4], b[4][2];
#pragma unroll
            for (int mt = 0; mt < 4; mt++) {
                const int rm = wm * 64 + mt * 16 + g;
                a[mt][0] = __float_as_uint(As[rm][kk]);
                a[mt][1] = __float_as_uint(As[rm + 8][kk]);
                a[mt][2] = __float_as_uint(As[rm][kk + 4]);
                a[mt][3] = __float_as_uint(As[rm + 8][kk + 4]);
            }
#pragma unroll
            for (int nt = 0; nt < 4; nt++) {
                const int rn = wn * 32 + nt * 8 + g;
                b[nt][0] = __float_as_uint(Ws[rn][kk]);
                b[nt][1] = __float_as_uint(Ws[rn][kk + 4]);
            }
#pragma unroll
            for (int mt = 0; mt < 4; mt++)
#pragma unroll
                for (int nt = 0; nt < 4; nt++) {
                    asm volatile(
                        "mma.sync.aligned.m16n8k8.row.col.f32.tf32.tf32.f32 "
                        "{%0,%1,%2,%3}, {%4,%5,%6,%7}, {%8,%9}, {%0,%1,%2,%3};"
                        : "+f"(acc[mt][nt][0]), "+f"(acc[mt][nt][1]),
                          "+f"(acc[mt][nt][2]), "+f"(acc[mt][nt][3])
                        : "r"(a[mt][0]), "r"(a[mt][1]), "r"(a[mt][2]), "r"(a[mt][3]),
                          "r"(b[nt][0]), "r"(b[nt][1]));
                }
        }
    }

#pragma unroll
    for (int mt = 0; mt < 4; mt++) {
#pragma unroll
        for (int nt = 0; nt < 4; nt++) {
            const int row0 = m0 + wm * 64 + mt * 16 + g;
            const int col0 = n0 + wn * 32 + nt * 8 + 2 * tg;
            store_elem(C, bias, masks, mode, scale, z, N, row0,     col0,     acc[mt][nt][0]);
            store_elem(C, bias, masks, mode, scale, z, N, row0,     col0 + 1, acc[mt][nt][1]);
            store_elem(C, bias, masks, mode, scale, z, N, row0 + 8, col0,     acc[mt][nt][2]);
            store_elem(C, bias, masks, mode, scale, z, N, row0 + 8, col0 + 1, acc[mt][nt][3]);
        }
    }
}

// ------------------------- flag reset -------------------------
__global__ void reset_kernel() {
    g_flag[blockIdx.x * 256 + threadIdx.x] = 0u;
}

// ------------------------- persistent GRU -------------------------
// (unchanged from round 5 — swizzled smem, per-rank L2 release flags)
__global__ void __launch_bounds__(384, 1) gru_kernel(
    const float* __restrict__ whf, const float* __restrict__ whb,
    const float* __restrict__ bhf, const float* __restrict__ bhb,
    const int* __restrict__ masks, float* __restrict__ hid_out)
{
    __shared__ float sh_h[1024];     // [b][swizzled k] h for 4 batches
    __shared__ float sh_part[1536];  // [r][b][kq]
    __shared__ float sh_gate[384];   // [r][b]

    const int bid = blockIdx.x;
    const int dir = bid >> 6;
    const int rem = bid & 63;
    const int bg  = rem >> 3;
    const int jc  = rem & 7;
    const int grp = dir * 8 + bg;
    const int tid = threadIdx.x;
    const int r   = tid >> 2;
    const int kq  = tid & 3;
    const int G   = (r >> 5) * 256 + jc * 32 + (r & 31);

    const float* wh = dir ? whb : whf;
    const float* bh = dir ? bhb : bhf;
    const float bhh = bh[G];

    unsigned long long wp[32];
    {
        const float* ws = wh + (long)G * NH2 + kq * 64;
#pragma unroll
        for (int i = 0; i < 32; i++) wp[i] = pack2(ws[2 * i], ws[2 * i + 1]);
    }

    const int ju = tid & 31, bu = tid >> 5;
    const int jglob = jc * 32 + ju;
    const int bglob = bg * 4 + bu;
    const float* xgp = g_xg + ((size_t)dir * NB + bglob) * NS * NG3;
    float* hxg = g_hx + grp * 2048;
    unsigned* myflag = &g_flag[(grp * 8 + jc) * 32];

    const int cb = tid >> 6, cc0 = tid & 63;
    const int csw = ((cc0 >> 4) << 4) | ((cc0 & 15) ^ (cc0 >> 4));
    float* shdst = &sh_h[cb * 256 + csw * 4];

    for (int i = tid; i < 1024; i += 384) sh_h[i] = 0.f;
    float hreg = 0.f;
    __syncthreads();

    for (int t = 0; t < NS; t++) {
        const int s = dir ? (NS - 1 - t) : t;
        float xr = 0.f, xz = 0.f, xn = 0.f;
        int mk = 0;
        if (tid < 128) {
            const float* xrow = xgp + (size_t)s * NG3;
            xr = __ldg(xrow + jglob);
            xz = __ldg(xrow + NH2 + jglob);
            xn = __ldg(xrow + 2 * NH2 + jglob);
            mk = __ldg(masks + bglob * NS + s);
        }
        if (t > 0) {
            if (tid < 8) {
                const unsigned* fp = &g_flag[(grp * 8 + tid) * 32];
                unsigned v;
                do {
                    asm volatile("ld.global.acquire.gpu.u32 %0, [%1];"
                                 : "=r"(v) : "l"(fp) : "memory");
                } while (v < (unsigned)t);
            }
            __syncthreads();
            if (tid < 256) {
                const float4* src = (const float4*)(hxg + ((t - 1) & 1) * 1024);
                float4 hv4;
                asm volatile("ld.global.cg.v4.f32 {%0,%1,%2,%3}, [%4];"
                             : "=f"(hv4.x), "=f"(hv4.y), "=f"(hv4.z), "=f"(hv4.w)
                             : "l"(src + tid) : "memory");
                *(float4*)shdst = hv4;
            }
            __syncthreads();
        }
        unsigned long long acc[4] = {0ull, 0ull, 0ull, 0ull};
#pragma unroll
        for (int i = 0; i < 16; i++) {
            const int coff = ((kq << 4) | (i ^ kq)) * 4;
#pragma unroll
            for (int b = 0; b < 4; b++) {
                ulonglong2 hv = *(const ulonglong2*)(sh_h + b * 256 + coff);
                acc[b] = fma2(wp[2 * i],     hv.x, acc[b]);
                acc[b] = fma2(wp[2 * i + 1], hv.y, acc[b]);
            }
        }
#pragma unroll
        for (int b = 0; b < 4; b++) {
            float lo, hi;
            unpack2(acc[b], lo, hi);
            sh_part[r * 16 + b * 4 + kq] = lo + hi;
        }
        __syncthreads();
        {
            const int base = r * 16 + kq * 4;
            sh_gate[r * 4 + kq] = sh_part[base] + sh_part[base + 1] +
                                  sh_part[base + 2] + sh_part[base + 3] + bhh;
        }
        __syncthreads();
        if (tid < 128) {
            const float hgr = sh_gate[ju * 4 + bu];
            const float hgz = sh_gate[(32 + ju) * 4 + bu];
            const float hgn = sh_gate[(64 + ju) * 4 + bu];
            const float rr = 1.f / (1.f + __expf(-(xr + hgr)));
            const float zz = 1.f / (1.f + __expf(-(xz + hgz)));
            const float na = xn + rr * hgn;
            const float nn = 2.f / (1.f + __expf(-2.f * na)) - 1.f;
            const float hnew = (1.f - zz) * nn + zz * hreg;
            hreg = mk ? hnew : hreg;
            g_gru[((size_t)bglob * NS + s) * ND + dir * NH2 + jglob] = mk ? hreg : 0.f;
            if (t == NS - 1) {
                hid_out[bglob * ND + dir * NH2 + jglob] = hreg;
            } else {
                __stcg(hxg + (t & 1) * 1024 + bu * 256 + jglob, hreg);
            }
        }
        if (t < NS - 1) {
            __syncthreads();
            if (tid == 0) {
                __threadfence();
                unsigned nv = (unsigned)(t + 1);
                asm volatile("st.global.cg.u32 [%0], %1;"
                             :: "l"(myflag), "r"(nv) : "memory");
            }
        }
    }
}

// ------------------------- layernorm (optionally fused residual) -------------------------
__global__ void __launch_bounds__(128) ln_kernel(
    const float* __restrict__ x, const float* __restrict__ y,
    const float* __restrict__ gam, const float* __restrict__ bet,
    float* __restrict__ out)
{
    __shared__ float red[8];
    const int row = blockIdx.x;
    const int tid = threadIdx.x;
    float4 v = *(const float4*)(x + (size_t)row * ND + tid * 4);
    if (y) {
        float4 w = *(const float4*)(y + (size_t)row * ND + tid * 4);
        v.x += w.x; v.y += w.y; v.z += w.z; v.w += w.w;
    }
    float s1 = v.x + v.y + v.z + v.w;
    float s2 = v.x * v.x + v.y * v.y + v.z * v.z + v.w * v.w;
#pragma unroll
    for (int o = 16; o; o >>= 1) {
        s1 += __shfl_xor_sync(~0u, s1, o);
        s2 += __shfl_xor_sync(~0u, s2, o);
    }
    const int wid = tid >> 5;
    if ((tid & 31) == 0) { red[wid] = s1; red[wid + 4] = s2; }
    __syncthreads();
    s1 = red[0] + red[1] + red[2] + red[3];
    s2 = red[4] + red[5] + red[6] + red[7];
    const float mu = s1 * (1.f / ND);
    const float var = s2 * (1.f / ND) - mu * mu;
    const float rs = rsqrtf(var + 1e-5f);
    const float4 gv = *(const float4*)(gam + tid * 4);
    const float4 bv = *(const float4*)(bet + tid * 4);
    float4 o4;
    o4.x = (v.x - mu) * rs * gv.x + bv.x;
    o4.y = (v.y - mu) * rs * gv.y + bv.y;
    o4.z = (v.z - mu) * rs * gv.z + bv.z;
    o4.w = (v.w - mu) * rs * gv.w + bv.w;
    *(float4*)(out + (size_t)row * ND + tid * 4) = o4;
}

// ------------------------- masked prefix softmax -------------------------
__global__ void __launch_bounds__(128) softmax_kernel(
    float* __restrict__ P, const int* __restrict__ lengths)
{
    __shared__ float red[4];
    const int q = blockIdx.x, z = blockIdx.y;
    const int len = __ldg(lengths + (z >> 3));
    float* row = P + ((size_t)z * NS + q) * NS;
    const int tid = threadIdx.x;
    const int c0 = tid * 4;
    if (q >= len) {
        *(float4*)(row + c0) = make_float4(0.f, 0.f, 0.f, 0.f);
        return;
    }
    float4 v = *(const float4*)(row + c0);
    const bool b0 = c0 < len, b1 = c0 + 1 < len, b2 = c0 + 2 < len, b3 = c0 + 3 < len;
    float m = -1e30f;
    if (b0) m = fmaxf(m, v.x);
    if (b1) m = fmaxf(m, v.y);
    if (b2) m = fmaxf(m, v.z);
    if (b3) m = fmaxf(m, v.w);
#pragma unroll
    for (int o = 16; o; o >>= 1) m = fmaxf(m, __shfl_xor_sync(~0u, m, o));
    const int wid = tid >> 5;
    if ((tid & 31) == 0) red[wid] = m;
    __syncthreads();
    m = fmaxf(fmaxf(red[0], red[1]), fmaxf(red[2], red[3]));
    __syncthreads();
    float4 e;
    e.x = b0 ? __expf(v.x - m) : 0.f;
    e.y = b1 ? __expf(v.y - m) : 0.f;
    e.z = b2 ? __expf(v.z - m) : 0.f;
    e.w = b3 ? __expf(v.w - m) : 0.f;
    float s = e.x + e.y + e.z + e.w;
#pragma unroll
    for (int o = 16; o; o >>= 1) s += __shfl_xor_sync(~0u, s, o);
    if ((tid & 31) == 0) red[wid] = s;
    __syncthreads();
    s = red[0] + red[1] + red[2] + red[3];
    const float inv = 1.f / s;
    e.x *= inv; e.y *= inv; e.z *= inv; e.w *= inv;
    *(float4*)(row + c0) = e;
}

// ------------------------- launch -------------------------
extern "C" void kernel_launch(void* const* d_in, const int* in_sizes, int n_in,
                              void* d_out, int out_size)
{
    const float* splits = (const float*)d_in[0];
    const float* w_ih_f = (const float*)d_in[1];
    const float* w_hh_f = (const float*)d_in[2];
    const float* b_ih_f = (const float*)d_in[3];
    const float* b_hh_f = (const float*)d_in[4];
    const float* w_ih_b = (const float*)d_in[5];
    const float* w_hh_b = (const float*)d_in[6];
    const float* b_ih_b = (const float*)d_in[7];
    const float* b_hh_b = (const float*)d_in[8];
    const float* ln1_g  = (const float*)d_in[9];
    const float* ln1_b  = (const float*)d_in[10];
    const float* wq = (const float*)d_in[11];
    const float* bq = (const float*)d_in[12];
    const float* wk = (const float*)d_in[13];
    const float* bk = (const float*)d_in[14];
    const float* wv = (const float*)d_in[15];
    const float* bv = (const float*)d_in[16];
    const float* wo = (const float*)d_in[17];
    const float* bo = (const float*)d_in[18];
    const float* ln2_g = (const float*)d_in[19];
    const float* ln2_b = (const float*)d_in[20];
    const int* lengths = (const int*)d_in[21];
    const int* masks   = (const int*)d_in[22];
    float* out = (float*)d_out;

    float *xg, *gru, *ln1, *q, *k, *vt, *sc, *cc, *oo;
    cudaGetSymbolAddress((void**)&xg,  g_xg);
    cudaGetSymbolAddress((void**)&gru, g_gru);
    cudaGetSymbolAddress((void**)&ln1, g_ln1);
    cudaGetSymbolAddress((void**)&q,   g_q);
    cudaGetSymbolAddress((void**)&k,   g_k);
    cudaGetSymbolAddress((void**)&vt,  g_vt);
    cudaGetSymbolAddress((void**)&sc,  g_sc);
    cudaGetSymbolAddress((void**)&cc,  g_cc);
    cudaGetSymbolAddress((void**)&oo,  g_o);

    const int M = NB * NS;  // 16384

    // GRU input projections (both dirs) — fp32 (feeds the recurrence)
    gemm_tn<<<dim3(6, 128, 1), 256>>>(splits, w_ih_f, b_ih_f, xg,
                                      M, NG3, ND, 0, 0, 0, 0, 1.f, nullptr);
    gemm_tn<<<dim3(6, 128, 1), 256>>>(splits, w_ih_b, b_ih_b, xg + (size_t)M * NG3,
                                      M, NG3, ND, 0, 0, 0, 0, 1.f, nullptr);
    // GRU recurrence (persistent, per-rank flag sync through L2)
    reset_kernel<<<16, 256>>>();
    gru_kernel<<<128, 384>>>(w_hh_f, w_hh_b, b_hh_f, b_hh_b, masks,
                             out + (size_t)NB * NS * ND);
    // LN1
    ln_kernel<<<M, 128>>>(gru, nullptr, ln1_g, ln1_b, ln1);
    // Q/K/V projections with head scatter — tf32 tensor cores
    gemm_tf32<<<dim3(4, 128, 1), 256>>>(ln1, wq, bq, q,  M, ND, ND, 0, 0, 0, 1, 1.f, nullptr);
    gemm_tf32<<<dim3(4, 128, 1), 256>>>(ln1, wk, bk, k,  M, ND, ND, 0, 0, 0, 1, 1.f, nullptr);
    gemm_tf32<<<dim3(4, 128, 1), 256>>>(ln1, wv, bv, vt, M, ND, ND, 0, 0, 0, 2, 1.f, nullptr);
    // scores = q @ k^T / 8   (z = b*8+h) — tf32
    gemm_tf32<<<dim3(4, 4, 256), 256>>>(q, k, nullptr, sc, NS, NS, NDK,
                                        (long)NS * NDK, (long)NS * NDK, (long)NS * NS,
                                        3, 0.125f, nullptr);
    // masked prefix softmax (in place)
    softmax_kernel<<<dim3(NS, 256), 128>>>(sc, lengths);
    // attn = p @ v  -> concat layout — tf32
    gemm_tf32<<<dim3(1, 4, 256), 256>>>(sc, vt, nullptr, cc, NS, NDK, NS,
                                        (long)NS * NS, (long)NS * NDK, 0,
                                        4, 1.f, nullptr);
    // out projection + row mask — tf32
    gemm_tf32<<<dim3(4, 128, 1), 256>>>(cc, wo, bo, oo, M, ND, ND, 0, 0, 0, 5, 1.f, masks);
    // residual + LN2 -> final outputs
    ln_kernel<<<M, 128>>>(ln1, oo, ln2_g, ln2_b, out);
}

// round 7
// speedup vs baseline: 3.9903x; 1.2782x over previous
#include <cuda_runtime.h>
#include <cstdint>
#include <cstddef>

#define NB   32
#define NS   512
#define ND   512
#define NH2  256
#define NG3  768
#define NDK  64

// ------------------------- scratch (device globals) -------------------------
__device__ float g_xg[(size_t)2 * NB * NS * NG3];   // gate preactivations, per dir
__device__ float g_gru[(size_t)NB * NS * ND];       // concat GRU outputs
__device__ float g_ln1[(size_t)NB * NS * ND];       // ln1("outputs")
__device__ float g_q [(size_t)NB * 8 * NS * NDK];   // (b,h,s,d)
__device__ float g_k [(size_t)NB * 8 * NS * NDK];   // (b,h,s,d)
__device__ float g_vt[(size_t)NB * 8 * NDK * NS];   // (b,h,d,s)
__device__ float g_sc[(size_t)NB * 8 * NS * NS];    // scores -> p
__device__ float g_cc[(size_t)NB * NS * ND];        // attn concat
__device__ float g_o [(size_t)NB * NS * ND];        // out projection
__device__ float g_hx[16 * 2048];                   // h exchange (16 groups x 2 bufs x 1024)
__device__ unsigned g_flag[16 * 8 * 32];            // per (group,rank) step flag, 1 per 128B line

// ------------------------- f32x2 helpers -------------------------
__device__ __forceinline__ unsigned long long fma2(unsigned long long a,
                                                   unsigned long long b,
                                                   unsigned long long c) {
    unsigned long long d;
    asm("fma.rn.f32x2 %0, %1, %2, %3;" : "=l"(d) : "l"(a), "l"(b), "l"(c));
    return d;
}
__device__ __forceinline__ unsigned long long pack2(float x, float y) {
    unsigned long long d;
    asm("mov.b64 %0, {%1, %2};" : "=l"(d) : "f"(x), "f"(y));
    return d;
}
__device__ __forceinline__ void unpack2(unsigned long long v, float& x, float& y) {
    asm("mov.b64 {%0, %1}, %2;" : "=f"(x), "=f"(y) : "l"(v));
}
__device__ __forceinline__ float tf32r(float f) {
    unsigned u;
    asm("cvt.rna.tf32.f32 %0, %1;" : "=r"(u) : "f"(f));
    return __uint_as_float(u);
}

// ------------------------- epilogue store -------------------------
// modes:
// 0: +bias              1: +bias, scatter (b,h,s,d)   2: +bias, scatter (b,h,d,s)
// 3: *scale             4: scatter concat (b,s,h*64+d) 5: +bias, *rowmask(masks)
__device__ __forceinline__ void store_elem(float* C, const float* bias,
                                           const int* masks, int mode, float scale,
                                           int z, int N, int mrow, int nc, float v) {
    if (nc >= N) return;
    if (mode == 0) {
        C[(long)mrow * N + nc] = v + bias[nc];
    } else if (mode == 1) {
        int b = mrow >> 9, s = mrow & 511, h = nc >> 6, d = nc & 63;
        C[(((long)(b * 8 + h) * NS + s)) * NDK + d] = v + bias[nc];
    } else if (mode == 2) {
        int b = mrow >> 9, s = mrow & 511, h = nc >> 6, d = nc & 63;
        C[((long)(b * 8 + h) * NDK + d) * NS + s] = v + bias[nc];
    } else if (mode == 3) {
        C[(long)mrow * N + nc] = v * scale;
    } else if (mode == 4) {
        int b = z >> 3, h = z & 7;
        C[((long)(b * NS + mrow)) * ND + h * NDK + nc] = v;
    } else {
        C[(long)mrow * N + nc] = masks[mrow] ? (v + bias[nc]) : 0.f;
    }
}

// ------------------------- tf32 tensor-core TN GEMM -------------------------
// C = epi(A[M,K] @ W[N,K]^T) via mma.sync.m16n8k8 tf32.
// 128x128x16 tile, 256 thr = 8 warps (2x4), each warp 64x32.
__global__ void __launch_bounds__(256) gemm_tf32(
    const float* __restrict__ A, const float* __restrict__ W,
    const float* __restrict__ bias, float* __restrict__ C,
    int M, int N, int K, long sA, long sW, long sC,
    int mode, float scale, const int* __restrict__ masks)
{
    __shared__ float As[128][20];   // [m][k], pad 20 -> conflict-free frag loads
    __shared__ float Ws[128][20];   // [n][k]

    const int z = blockIdx.z;
    A += (long)z * sA;
    W += (long)z * sW;
    if (mode == 3) C += (long)z * sC;

    const int m0 = blockIdx.y * 128, n0 = blockIdx.x * 128;
    const int tid  = threadIdx.x;
    const int warp = tid >> 5, lane = tid & 31;
    const int wm = warp >> 2, wn = warp & 3;   // warp grid 2 x 4
    const int g  = lane >> 2, tg = lane & 3;   // mma group / thread-in-group

    const int lm = tid >> 2, lkq = tid & 3;
    const float* Aip = A + (long)(m0 + lm) * K + lkq * 4;
    const float* Wip = W + (long)(n0 + lm) * K + lkq * 4;
    const bool w0ok = (n0 + lm) < N;
    const bool w1ok = (n0 + lm + 64) < N;
    const float4 z4 = make_float4(0.f, 0.f, 0.f, 0.f);

    float acc[4][4][4];
#pragma unroll
    for (int mt = 0; mt < 4; mt++)
#pragma unroll
        for (int nt = 0; nt < 4; nt++)
#pragma unroll
            for (int c = 0; c < 4; c++) acc[mt][nt][c] = 0.f;

    float4 a0v = *(const float4*)Aip;
    float4 a1v = *(const float4*)(Aip + (long)64 * K);
    float4 w0v = w0ok ? *(const float4*)Wip : z4;
    float4 w1v = w1ok ? *(const float4*)(Wip + (long)64 * K) : z4;

    for (int k0 = 0; k0 < K; k0 += 16) {
        __syncthreads();
        {
            float* pa0 = &As[lm][lkq * 4];
            pa0[0] = tf32r(a0v.x); pa0[1] = tf32r(a0v.y);
            pa0[2] = tf32r(a0v.z); pa0[3] = tf32r(a0v.w);
            float* pa1 = &As[lm + 64][lkq * 4];
            pa1[0] = tf32r(a1v.x); pa1[1] = tf32r(a1v.y);
            pa1[2] = tf32r(a1v.z); pa1[3] = tf32r(a1v.w);
            float* pw0 = &Ws[lm][lkq * 4];
            pw0[0] = tf32r(w0v.x); pw0[1] = tf32r(w0v.y);
            pw0[2] = tf32r(w0v.z); pw0[3] = tf32r(w0v.w);
            float* pw1 = &Ws[lm + 64][lkq * 4];
            pw1[0] = tf32r(w1v.x); pw1[1] = tf32r(w1v.y);
            pw1[2] = tf32r(w1v.z); pw1[3] = tf32r(w1v.w);
        }
        __syncthreads();
        if (k0 + 16 < K) {
            a0v = *(const float4*)(Aip + k0 + 16);
            a1v = *(const float4*)(Aip + (long)64 * K + k0 + 16);
            w0v = w0ok ? *(const float4*)(Wip + k0 + 16) : z4;
            w1v = w1ok ? *(const float4*)(Wip + (long)64 * K + k0 + 16) : z4;
        }
#pragma unroll
        for (int kb = 0; kb < 2; kb++) {
            const int kk = kb * 8 + tg;
            unsigned a[4][4], b[4][2];
#pragma unroll
            for (int mt = 0; mt < 4; mt++) {
                const int rm = wm * 64 + mt * 16 + g;
                a[mt][0] = __float_as_uint(As[rm][kk]);
                a[mt][1] = __float_as_uint(As[rm + 8][kk]);
                a[mt][2] = __float_as_uint(As[rm][kk + 4]);
                a[mt][3] = __float_as_uint(As[rm + 8][kk + 4]);
            }
#pragma unroll
            for (int nt = 0; nt < 4; nt++) {
                const int rn = wn * 32 + nt * 8 + g;
                b[nt][0] = __float_as_uint(Ws[rn][kk]);
                b[nt][1] = __float_as_uint(Ws[rn][kk + 4]);
            }
#pragma unroll
            for (int mt = 0; mt < 4; mt++)
#pragma unroll
                for (int nt = 0; nt < 4; nt++) {
                    asm volatile(
                        "mma.sync.aligned.m16n8k8.row.col.f32.tf32.tf32.f32 "
                        "{%0,%1,%2,%3}, {%4,%5,%6,%7}, {%8,%9}, {%0,%1,%2,%3};"
                        : "+f"(acc[mt][nt][0]), "+f"(acc[mt][nt][1]),
                          "+f"(acc[mt][nt][2]), "+f"(acc[mt][nt][3])
                        : "r"(a[mt][0]), "r"(a[mt][1]), "r"(a[mt][2]), "r"(a[mt][3]),
                          "r"(b[nt][0]), "r"(b[nt][1]));
                }
        }
    }

#pragma unroll
    for (int mt = 0; mt < 4; mt++) {
#pragma unroll
        for (int nt = 0; nt < 4; nt++) {
            const int row0 = m0 + wm * 64 + mt * 16 + g;
            const int col0 = n0 + wn * 32 + nt * 8 + 2 * tg;
            store_elem(C, bias, masks, mode, scale, z, N, row0,     col0,     acc[mt][nt][0]);
            store_elem(C, bias, masks, mode, scale, z, N, row0,     col0 + 1, acc[mt][nt][1]);
            store_elem(C, bias, masks, mode, scale, z, N, row0 + 8, col0,     acc[mt][nt][2]);
            store_elem(C, bias, masks, mode, scale, z, N, row0 + 8, col0 + 1, acc[mt][nt][3]);
        }
    }
}

// ------------------------- flag reset -------------------------
__global__ void reset_kernel() {
    g_flag[blockIdx.x * 256 + threadIdx.x] = 0u;
}

// ------------------------- persistent GRU -------------------------
// 128 blocks = dir(2) x batchgroup(8 of 4 batches) x jchunk(8 of 32 j).
// 384 threads = rg(48, 2 gate-rows each) x ks(8, 32-k slice each).
// Weights register-resident; h in smem with XOR swizzle
// (chunk (ks<<3)|(i^ks)) so each LDS.128 hits all 8 bank groups (full 128B
// wavefronts). Reduction over ks via 3 butterfly shuffles (no smem).
// h exchanged across the 8 j-chunk blocks via L2 (st.cg) + per-rank flags.
__global__ void __launch_bounds__(384, 1) gru_kernel(
    const float* __restrict__ whf, const float* __restrict__ whb,
    const float* __restrict__ bhf, const float* __restrict__ bhb,
    const int* __restrict__ masks, float* __restrict__ hid_out)
{
    __shared__ float sh_h[1024];     // [b][swizzled k] h for 4 batches
    __shared__ float sh_gate[384];   // [row][b]

    const int bid = blockIdx.x;
    const int dir = bid >> 6;
    const int rem = bid & 63;
    const int bg  = rem >> 3;
    const int jc  = rem & 7;
    const int grp = dir * 8 + bg;
    const int tid = threadIdx.x;
    const int rg  = tid >> 3;        // 0..47 (gate-row pair)
    const int ks  = tid & 7;         // k eighth (32 values)
    const int row0 = rg * 2, row1 = rg * 2 + 1;
    const int G0 = (row0 >> 5) * 256 + jc * 32 + (row0 & 31);
    const int G1 = (row1 >> 5) * 256 + jc * 32 + (row1 & 31);

    const float* wh = dir ? whb : whf;
    const float* bh = dir ? bhb : bhf;
    const float bh0 = bh[G0], bh1 = bh[G1];

    unsigned long long wp0[16], wp1[16];
    {
        const float* w0s = wh + (long)G0 * NH2 + ks * 32;
        const float* w1s = wh + (long)G1 * NH2 + ks * 32;
#pragma unroll
        for (int i = 0; i < 16; i++) {
            wp0[i] = pack2(w0s[2 * i], w0s[2 * i + 1]);
            wp1[i] = pack2(w1s[2 * i], w1s[2 * i + 1]);
        }
    }

    const int ju = tid & 31, bu = tid >> 5;   // updater role (tid < 128)
    const int jglob = jc * 32 + ju;
    const int bglob = bg * 4 + bu;
    const float* xgp = g_xg + ((size_t)dir * NB + bglob) * NS * NG3;
    float* hxg = g_hx + grp * 2048;
    unsigned* myflag = &g_flag[(grp * 8 + jc) * 32];

    // consumer-copy swizzled destination (tid<256): logical chunk cc0 ->
    // physical ((cc0>>3)<<3) | ((cc0&7) ^ (cc0>>3))
    const int cb = tid >> 6, cc0 = tid & 63;
    const int csw = ((cc0 >> 3) << 3) | ((cc0 & 7) ^ (cc0 >> 3));
    float* shdst = &sh_h[cb * 256 + csw * 4];

    for (int i = tid; i < 1024; i += 384) sh_h[i] = 0.f;
    float hreg = 0.f;
    __syncthreads();

    for (int t = 0; t < NS; t++) {
        const int s = dir ? (NS - 1 - t) : t;
        float xr = 0.f, xz = 0.f, xn = 0.f;
        int mk = 0;
        if (tid < 128) {  // prefetch x-gates + mask (independent of h)
            const float* xrow = xgp + (size_t)s * NG3;
            xr = __ldg(xrow + jglob);
            xz = __ldg(xrow + NH2 + jglob);
            xn = __ldg(xrow + 2 * NH2 + jglob);
            mk = __ldg(masks + bglob * NS + s);
        }
        if (t > 0) {
            if (tid < 8) {  // one spinner per producer rank, distinct L2 lines
                const unsigned* fp = &g_flag[(grp * 8 + tid) * 32];
                unsigned v;
                do {
                    asm volatile("ld.global.acquire.gpu.u32 %0, [%1];"
                                 : "=r"(v) : "l"(fp) : "memory");
                } while (v < (unsigned)t);
            }
            __syncthreads();
            if (tid < 256) {
                const float4* src = (const float4*)(hxg + ((t - 1) & 1) * 1024);
                float4 hv4;
                asm volatile("ld.global.cg.v4.f32 {%0,%1,%2,%3}, [%4];"
                             : "=f"(hv4.x), "=f"(hv4.y), "=f"(hv4.z), "=f"(hv4.w)
                             : "l"(src + tid) : "memory");
                *(float4*)shdst = hv4;
            }
            __syncthreads();
        }
        // gate dot products: 2 gate-rows x 4 batches, k slice ks*32..+31
        unsigned long long a0[4] = {0ull, 0ull, 0ull, 0ull};
        unsigned long long a1[4] = {0ull, 0ull, 0ull, 0ull};
#pragma unroll
        for (int i = 0; i < 8; i++) {
            const int coff = (((ks << 3) | (i ^ ks)) << 2);
#pragma unroll
            for (int b = 0; b < 4; b++) {
                ulonglong2 hv = *(const ulonglong2*)(sh_h + b * 256 + coff);
                a0[b] = fma2(wp0[2 * i],     hv.x, a0[b]);
                a0[b] = fma2(wp0[2 * i + 1], hv.y, a0[b]);
                a1[b] = fma2(wp1[2 * i],     hv.x, a1[b]);
                a1[b] = fma2(wp1[2 * i + 1], hv.y, a1[b]);
            }
        }
        float v0[4], v1[4];
#pragma unroll
        for (int b = 0; b < 4; b++) {
            float lo, hi;
            unpack2(a0[b], lo, hi); v0[b] = lo + hi;
            unpack2(a1[b], lo, hi); v1[b] = lo + hi;
        }
        // butterfly-reduce over the 8 ks lanes
#pragma unroll
        for (int off = 1; off < 8; off <<= 1) {
#pragma unroll
            for (int b = 0; b < 4; b++) {
                v0[b] += __shfl_xor_sync(~0u, v0[b], off);
                v1[b] += __shfl_xor_sync(~0u, v1[b], off);
            }
        }
        if (ks == 0) {
            float4 f0 = make_float4(v0[0] + bh0, v0[1] + bh0, v0[2] + bh0, v0[3] + bh0);
            float4 f1 = make_float4(v1[0] + bh1, v1[1] + bh1, v1[2] + bh1, v1[3] + bh1);
            *(float4*)&sh_gate[rg * 8]     = f0;
            *(float4*)&sh_gate[rg * 8 + 4] = f1;
        }
        __syncthreads();
        if (tid < 128) {
            const float hgr = sh_gate[ju * 4 + bu];
            const float hgz = sh_gate[(32 + ju) * 4 + bu];
            const float hgn = sh_gate[(64 + ju) * 4 + bu];
            const float rr = 1.f / (1.f + __expf(-(xr + hgr)));
            const float zz = 1.f / (1.f + __expf(-(xz + hgz)));
            const float na = xn + rr * hgn;
            const float nn = 2.f / (1.f + __expf(-2.f * na)) - 1.f;  // tanh
            const float hnew = (1.f - zz) * nn + zz * hreg;
            hreg = mk ? hnew : hreg;
            g_gru[((size_t)bglob * NS + s) * ND + dir * NH2 + jglob] = mk ? hreg : 0.f;
            if (t == NS - 1) {
                hid_out[bglob * ND + dir * NH2 + jglob] = hreg;
            } else {
                __stcg(hxg + (t & 1) * 1024 + bu * 256 + jglob, hreg);
            }
        }
        if (t < NS - 1) {
            __syncthreads();     // all h stores program-ordered before here
            if (tid == 0) {
                __threadfence();  // cumulative: orders the block's stores gpu-wide
                unsigned nv = (unsigned)(t + 1);
                asm volatile("st.global.cg.u32 [%0], %1;"
                             :: "l"(myflag), "r"(nv) : "memory");
            }
        }
    }
}

// ------------------------- layernorm (optionally fused residual) -------------------------
__global__ void __launch_bounds__(128) ln_kernel(
    const float* __restrict__ x, const float* __restrict__ y,
    const float* __restrict__ gam, const float* __restrict__ bet,
    float* __restrict__ out)
{
    __shared__ float red[8];
    const int row = blockIdx.x;
    const int tid = threadIdx.x;
    float4 v = *(const float4*)(x + (size_t)row * ND + tid * 4);
    if (y) {
        float4 w = *(const float4*)(y + (size_t)row * ND + tid * 4);
        v.x += w.x; v.y += w.y; v.z += w.z; v.w += w.w;
    }
    float s1 = v.x + v.y + v.z + v.w;
    float s2 = v.x * v.x + v.y * v.y + v.z * v.z + v.w * v.w;
#pragma unroll
    for (int o = 16; o; o >>= 1) {
        s1 += __shfl_xor_sync(~0u, s1, o);
        s2 += __shfl_xor_sync(~0u, s2, o);
    }
    const int wid = tid >> 5;
    if ((tid & 31) == 0) { red[wid] = s1; red[wid + 4] = s2; }
    __syncthreads();
    s1 = red[0] + red[1] + red[2] + red[3];
    s2 = red[4] + red[5] + red[6] + red[7];
    const float mu = s1 * (1.f / ND);
    const float var = s2 * (1.f / ND) - mu * mu;
    const float rs = rsqrtf(var + 1e-5f);
    const float4 gv = *(const float4*)(gam + tid * 4);
    const float4 bv = *(const float4*)(bet + tid * 4);
    float4 o4;
    o4.x = (v.x - mu) * rs * gv.x + bv.x;
    o4.y = (v.y - mu) * rs * gv.y + bv.y;
    o4.z = (v.z - mu) * rs * gv.z + bv.z;
    o4.w = (v.w - mu) * rs * gv.w + bv.w;
    *(float4*)(out + (size_t)row * ND + tid * 4) = o4;
}

// ------------------------- masked prefix softmax -------------------------
__global__ void __launch_bounds__(128) softmax_kernel(
    float* __restrict__ P, const int* __restrict__ lengths)
{
    __shared__ float red[4];
    const int q = blockIdx.x, z = blockIdx.y;
    const int len = __ldg(lengths + (z >> 3));
    float* row = P + ((size_t)z * NS + q) * NS;
    const int tid = threadIdx.x;
    const int c0 = tid * 4;
    if (q >= len) {
        *(float4*)(row + c0) = make_float4(0.f, 0.f, 0.f, 0.f);
        return;
    }
    float4 v = *(const float4*)(row + c0);
    const bool b0 = c0 < len, b1 = c0 + 1 < len, b2 = c0 + 2 < len, b3 = c0 + 3 < len;
    float m = -1e30f;
    if (b0) m = fmaxf(m, v.x);
    if (b1) m = fmaxf(m, v.y);
    if (b2) m = fmaxf(m, v.z);
    if (b3) m = fmaxf(m, v.w);
#pragma unroll
    for (int o = 16; o; o >>= 1) m = fmaxf(m, __shfl_xor_sync(~0u, m, o));
    const int wid = tid >> 5;
    if ((tid & 31) == 0) red[wid] = m;
    __syncthreads();
    m = fmaxf(fmaxf(red[0], red[1]), fmaxf(red[2], red[3]));
    __syncthreads();
    float4 e;
    e.x = b0 ? __expf(v.x - m) : 0.f;
    e.y = b1 ? __expf(v.y - m) : 0.f;
    e.z = b2 ? __expf(v.z - m) : 0.f;
    e.w = b3 ? __expf(v.w - m) : 0.f;
    float s = e.x + e.y + e.z + e.w;
#pragma unroll
    for (int o = 16; o; o >>= 1) s += __shfl_xor_sync(~0u, s, o);
    if ((tid & 31) == 0) red[wid] = s;
    __syncthreads();
    s = red[0] + red[1] + red[2] + red[3];
    const float inv = 1.f / s;
    e.x *= inv; e.y *= inv; e.z *= inv; e.w *= inv;
    *(float4*)(row + c0) = e;
}

// ------------------------- launch -------------------------
extern "C" void kernel_launch(void* const* d_in, const int* in_sizes, int n_in,
                              void* d_out, int out_size)
{
    const float* splits = (const float*)d_in[0];
    const float* w_ih_f = (const float*)d_in[1];
    const float* w_hh_f = (const float*)d_in[2];
    const float* b_ih_f = (const float*)d_in[3];
    const float* b_hh_f = (const float*)d_in[4];
    const float* w_ih_b = (const float*)d_in[5];
    const float* w_hh_b = (const float*)d_in[6];
    const float* b_ih_b = (const float*)d_in[7];
    const float* b_hh_b = (const float*)d_in[8];
    const float* ln1_g  = (const float*)d_in[9];
    const float* ln1_b  = (const float*)d_in[10];
    const float* wq = (const float*)d_in[11];
    const float* bq = (const float*)d_in[12];
    const float* wk = (const float*)d_in[13];
    const float* bk = (const float*)d_in[14];
    const float* wv = (const float*)d_in[15];
    const float* bv = (const float*)d_in[16];
    const float* wo = (const float*)d_in[17];
    const float* bo = (const float*)d_in[18];
    const float* ln2_g = (const float*)d_in[19];
    const float* ln2_b = (const float*)d_in[20];
    const int* lengths = (const int*)d_in[21];
    const int* masks   = (const int*)d_in[22];
    float* out = (float*)d_out;

    float *xg, *gru, *ln1, *q, *k, *vt, *sc, *cc, *oo;
    cudaGetSymbolAddress((void**)&xg,  g_xg);
    cudaGetSymbolAddress((void**)&gru, g_gru);
    cudaGetSymbolAddress((void**)&ln1, g_ln1);
    cudaGetSymbolAddress((void**)&q,   g_q);
    cudaGetSymbolAddress((void**)&k,   g_k);
    cudaGetSymbolAddress((void**)&vt,  g_vt);
    cudaGetSymbolAddress((void**)&sc,  g_sc);
    cudaGetSymbolAddress((void**)&cc,  g_cc);
    cudaGetSymbolAddress((void**)&oo,  g_o);

    const int M = NB * NS;  // 16384

    // GRU input projections (both dirs) — tf32 tensor cores
    gemm_tf32<<<dim3(6, 128, 1), 256>>>(splits, w_ih_f, b_ih_f, xg,
                                        M, NG3, ND, 0, 0, 0, 0, 1.f, nullptr);
    gemm_tf32<<<dim3(6, 128, 1), 256>>>(splits, w_ih_b, b_ih_b, xg + (size_t)M * NG3,
                                        M, NG3, ND, 0, 0, 0, 0, 1.f, nullptr);
    // GRU recurrence (persistent, per-rank flag sync through L2)
    reset_kernel<<<16, 256>>>();
    gru_kernel<<<128, 384>>>(w_hh_f, w_hh_b, b_hh_f, b_hh_b, masks,
                             out + (size_t)NB * NS * ND);
    // LN1
    ln_kernel<<<M, 128>>>(gru, nullptr, ln1_g, ln1_b, ln1);
    // Q/K/V projections with head scatter — tf32
    gemm_tf32<<<dim3(4, 128, 1), 256>>>(ln1, wq, bq, q,  M, ND, ND, 0, 0, 0, 1, 1.f, nullptr);
    gemm_tf32<<<dim3(4, 128, 1), 256>>>(ln1, wk, bk, k,  M, ND, ND, 0, 0, 0, 1, 1.f, nullptr);
    gemm_tf32<<<dim3(4, 128, 1), 256>>>(ln1, wv, bv, vt, M, ND, ND, 0, 0, 0, 2, 1.f, nullptr);
    // scores = q @ k^T / 8   (z = b*8+h) — tf32
    gemm_tf32<<<dim3(4, 4, 256), 256>>>(q, k, nullptr, sc, NS, NS, NDK,
                                        (long)NS * NDK, (long)NS * NDK, (long)NS * NS,
                                        3, 0.125f, nullptr);
    // masked prefix softmax (in place)
    softmax_kernel<<<dim3(NS, 256), 128>>>(sc, lengths);
    // attn = p @ v  -> concat layout — tf32
    gemm_tf32<<<dim3(1, 4, 256), 256>>>(sc, vt, nullptr, cc, NS, NDK, NS,
                                        (long)NS * NS, (long)NS * NDK, 0,
                                        4, 1.f, nullptr);
    // out projection + row mask — tf32
    gemm_tf32<<<dim3(4, 128, 1), 256>>>(cc, wo, bo, oo, M, ND, ND, 0, 0, 0, 5, 1.f, masks);
    // residual + LN2 -> final outputs
    ln_kernel<<<M, 128>>>(ln1, oo, ln2_g, ln2_b, out);
}